// round 1
// baseline (speedup 1.0000x reference)
#include <cuda_runtime.h>

#define NN 100000
#define NE 1200000
#define HH 64
#define H2 128

// ---------------- device scratch (no allocations allowed) ----------------
__device__ float g_z[NN * HH];   // layer input features
__device__ float g_h[NN * HH];   // residual stream
__device__ float g_u[NN * HH];   // agg + z (MLP input)
__device__ int   g_rowptr[NN + 1];
__device__ int   g_wp[NN];
__device__ int   g_srcs[NE];
__device__ int   g_bsums[128];

// ---------------- CSR build ----------------
__global__ void k_zero() {
    int i = blockIdx.x * blockDim.x + threadIdx.x;
    if (i < NN) g_wp[i] = 0;
}

__global__ void k_hist(const int* __restrict__ ei) {
    int e = blockIdx.x * blockDim.x + threadIdx.x;
    if (e < NE) atomicAdd(&g_wp[ei[NE + e]], 1);
}

__global__ void k_scan_reduce() {
    __shared__ int sd[1024];
    int i = blockIdx.x * 1024 + threadIdx.x;
    sd[threadIdx.x] = (i < NN) ? g_wp[i] : 0;
    __syncthreads();
    for (int s = 512; s > 0; s >>= 1) {
        if ((int)threadIdx.x < s) sd[threadIdx.x] += sd[threadIdx.x + s];
        __syncthreads();
    }
    if (threadIdx.x == 0) g_bsums[blockIdx.x] = sd[0];
}

__global__ void k_scan_mid(int nb) {
    if (threadIdx.x == 0 && blockIdx.x == 0) {
        int run = 0;
        for (int bb = 0; bb < nb; bb++) { int t = g_bsums[bb]; g_bsums[bb] = run; run += t; }
        g_rowptr[NN] = run;
    }
}

__global__ void k_scan_final() {
    __shared__ int buf0[1024], buf1[1024];
    int i = blockIdx.x * 1024 + threadIdx.x;
    int x = (i < NN) ? g_wp[i] : 0;
    buf0[threadIdx.x] = x;
    __syncthreads();
    int* cur = buf0; int* nxt = buf1;
    for (int d = 1; d < 1024; d <<= 1) {
        int v = cur[threadIdx.x];
        if ((int)threadIdx.x >= d) v += cur[threadIdx.x - d];
        nxt[threadIdx.x] = v;
        __syncthreads();
        int* tmp = cur; cur = nxt; nxt = tmp;
    }
    if (i < NN) g_rowptr[i] = g_bsums[blockIdx.x] + cur[threadIdx.x] - x;  // exclusive
}

__global__ void k_copy() {
    int i = blockIdx.x * blockDim.x + threadIdx.x;
    if (i < NN) g_wp[i] = g_rowptr[i];
}

__global__ void k_scatter(const int* __restrict__ ei) {
    int e = blockIdx.x * blockDim.x + threadIdx.x;
    if (e < NE) {
        int d = ei[NE + e];
        int p = atomicAdd(&g_wp[d], 1);
        g_srcs[p] = ei[e];
    }
}

// ---------------- encoder: g_z = x @ enc_W + enc_b ----------------
__global__ void k_enc(const float* __restrict__ x, const float* __restrict__ W,
                      const float* __restrict__ b) {
    int idx = blockIdx.x * blockDim.x + threadIdx.x;
    if (idx >= NN * HH) return;
    int n = idx >> 6, c = idx & 63;
    g_z[idx] = x[n * 3] * W[c] + x[n * 3 + 1] * W[HH + c] + x[n * 3 + 2] * W[2 * HH + c] + b[c];
}

// ---------------- softmax aggregation (warp per node, CSR, no atomics) ----
__global__ void k_agg(const float* __restrict__ tptr) {
    int gw = (blockIdx.x * blockDim.x + threadIdx.x) >> 5;
    if (gw >= NN) return;
    int lane = threadIdx.x & 31;
    int beg = g_rowptr[gw], end = g_rowptr[gw + 1];
    float tt = *tptr;

    float mx = -3e38f, my = -3e38f;
    for (int e = beg; e < end; e++) {
        int s = __ldg(&g_srcs[e]);
        float2 v = *(const float2*)(g_z + s * HH + 2 * lane);
        float ax = fmaxf(v.x, 0.f) + 1e-7f, ay = fmaxf(v.y, 0.f) + 1e-7f;
        mx = fmaxf(mx, ax * tt);
        my = fmaxf(my, ay * tt);
    }
    float zx = 0.f, zy = 0.f, sx = 0.f, sy = 0.f;
    for (int e = beg; e < end; e++) {
        int s = __ldg(&g_srcs[e]);
        float2 v = *(const float2*)(g_z + s * HH + 2 * lane);
        float ax = fmaxf(v.x, 0.f) + 1e-7f, ay = fmaxf(v.y, 0.f) + 1e-7f;
        float wx = __expf(ax * tt - mx), wy = __expf(ay * tt - my);
        zx += wx; zy += wy;
        sx += ax * wx; sy += ay * wy;
    }
    float2 zz = *(const float2*)(g_z + gw * HH + 2 * lane);
    float ux = (end > beg) ? sx / zx : 0.f;
    float uy = (end > beg) ? sy / zy : 0.f;
    float2 o = make_float2(ux + zz.x, uy + zz.y);
    *(float2*)(g_u + gw * HH + 2 * lane) = o;
}

// ---------------- outer pre-conv z = relu(LN(h)) ----------------
__global__ void k_lnrelu(const float* __restrict__ g, const float* __restrict__ b) {
    int gw = (blockIdx.x * blockDim.x + threadIdx.x) >> 5;
    if (gw >= NN) return;
    int lane = threadIdx.x & 31;
    float2 v = *(const float2*)(g_h + gw * HH + 2 * lane);
    float s = v.x + v.y, sq = v.x * v.x + v.y * v.y;
    for (int o = 16; o; o >>= 1) {
        s  += __shfl_xor_sync(0xffffffffu, s, o);
        sq += __shfl_xor_sync(0xffffffffu, sq, o);
    }
    float mu = s * 0.015625f;
    float var = sq * 0.015625f - mu * mu;
    float rs = rsqrtf(var + 1e-5f);
    float2 o2;
    o2.x = fmaxf((v.x - mu) * rs * g[2 * lane]     + b[2 * lane],     0.f);
    o2.y = fmaxf((v.y - mu) * rs * g[2 * lane + 1] + b[2 * lane + 1], 0.f);
    *(float2*)(g_z + gw * HH + 2 * lane) = o2;
}

// ---------------- fused MLP: u @ W1 + b1 -> LN -> relu -> @ W2 + b2 -------
// 64 nodes per block, 256 threads, weights in SMEM, reg tile 4 nodes x 8 ch.
extern __shared__ float smem[];
__global__ __launch_bounds__(256, 2) void k_mlp(
    const float* __restrict__ W1, const float* __restrict__ b1,
    const float* __restrict__ gam, const float* __restrict__ bet,
    const float* __restrict__ W2, const float* __restrict__ b2, int addm)
{
    float* sAB = smem;              // reused: sU[64][65] then sHd[128][65]
    float* sW1 = smem + H2 * 65;    // 64*128
    float* sW2 = sW1 + HH * H2;     // 128*64
    int tid = threadIdx.x;
    int n0  = blockIdx.x * 64;

    // load U (transposed-free layout [node][k], pitch 65)
    {
        int w = tid >> 5, l = tid & 31;
        for (int n = w; n < 64; n += 8) {
            int node = n0 + n;
            float2 v = make_float2(0.f, 0.f);
            if (node < NN) v = *(const float2*)(g_u + node * HH + 2 * l);
            sAB[n * 65 + 2 * l]     = v.x;
            sAB[n * 65 + 2 * l + 1] = v.y;
        }
    }
    // load weights
    {
        const float4* s1 = (const float4*)W1; float4* d1 = (float4*)sW1;
        for (int i = tid; i < HH * H2 / 4; i += 256) d1[i] = s1[i];
        const float4* s2 = (const float4*)W2; float4* d2 = (float4*)sW2;
        for (int i = tid; i < HH * H2 / 4; i += 256) d2[i] = s2[i];
    }
    __syncthreads();

    int tc = tid & 15, tn = tid >> 4;

    // GEMM1: hid[4 nodes][8 ch]
    float acc[4][8];
#pragma unroll
    for (int i = 0; i < 4; i++)
#pragma unroll
        for (int j = 0; j < 8; j++) acc[i][j] = 0.f;

#pragma unroll 8
    for (int k = 0; k < HH; k++) {
        float a0 = sAB[(4 * tn + 0) * 65 + k];
        float a1 = sAB[(4 * tn + 1) * 65 + k];
        float a2 = sAB[(4 * tn + 2) * 65 + k];
        float a3 = sAB[(4 * tn + 3) * 65 + k];
        float4 b0 = *(const float4*)&sW1[k * H2 + 8 * tc];
        float4 bb = *(const float4*)&sW1[k * H2 + 8 * tc + 4];
        float bv[8] = {b0.x, b0.y, b0.z, b0.w, bb.x, bb.y, bb.z, bb.w};
#pragma unroll
        for (int j = 0; j < 8; j++) {
            acc[0][j] += a0 * bv[j];
            acc[1][j] += a1 * bv[j];
            acc[2][j] += a2 * bv[j];
            acc[3][j] += a3 * bv[j];
        }
    }
    __syncthreads();

    // stash hidden transposed sHd[j][node] + bias
#pragma unroll
    for (int j = 0; j < 8; j++) {
        float bias = b1[8 * tc + j];
#pragma unroll
        for (int i = 0; i < 4; i++)
            sAB[(8 * tc + j) * 65 + 4 * tn + i] = acc[i][j] + bias;
    }
    __syncthreads();

    // LayerNorm(128) + relu, warp per node, in-place in sHd
    {
        int w = tid >> 5, l = tid & 31;
        float g0 = gam[l], g1 = gam[l + 32], g2 = gam[l + 64], g3 = gam[l + 96];
        float e0 = bet[l], e1 = bet[l + 32], e2 = bet[l + 64], e3 = bet[l + 96];
        for (int n = w; n < 64; n += 8) {
            float v0 = sAB[l * 65 + n];
            float v1 = sAB[(l + 32) * 65 + n];
            float v2 = sAB[(l + 64) * 65 + n];
            float v3 = sAB[(l + 96) * 65 + n];
            float s = v0 + v1 + v2 + v3;
            float sq = v0 * v0 + v1 * v1 + v2 * v2 + v3 * v3;
            for (int o = 16; o; o >>= 1) {
                s  += __shfl_xor_sync(0xffffffffu, s, o);
                sq += __shfl_xor_sync(0xffffffffu, sq, o);
            }
            float mu = s * (1.f / 128.f);
            float var = sq * (1.f / 128.f) - mu * mu;
            float rs = rsqrtf(var + 1e-5f);
            sAB[l * 65 + n]        = fmaxf((v0 - mu) * rs * g0 + e0, 0.f);
            sAB[(l + 32) * 65 + n] = fmaxf((v1 - mu) * rs * g1 + e1, 0.f);
            sAB[(l + 64) * 65 + n] = fmaxf((v2 - mu) * rs * g2 + e2, 0.f);
            sAB[(l + 96) * 65 + n] = fmaxf((v3 - mu) * rs * g3 + e3, 0.f);
        }
    }
    __syncthreads();

    // GEMM2: out[4 nodes][4 ch]
    float o4[4][4];
#pragma unroll
    for (int i = 0; i < 4; i++)
#pragma unroll
        for (int j = 0; j < 4; j++) o4[i][j] = 0.f;

#pragma unroll 8
    for (int k = 0; k < H2; k++) {
        float a0 = sAB[k * 65 + 4 * tn + 0];
        float a1 = sAB[k * 65 + 4 * tn + 1];
        float a2 = sAB[k * 65 + 4 * tn + 2];
        float a3 = sAB[k * 65 + 4 * tn + 3];
        float4 b = *(const float4*)&sW2[k * HH + 4 * tc];
        o4[0][0] += a0 * b.x; o4[0][1] += a0 * b.y; o4[0][2] += a0 * b.z; o4[0][3] += a0 * b.w;
        o4[1][0] += a1 * b.x; o4[1][1] += a1 * b.y; o4[1][2] += a1 * b.z; o4[1][3] += a1 * b.w;
        o4[2][0] += a2 * b.x; o4[2][1] += a2 * b.y; o4[2][2] += a2 * b.z; o4[2][3] += a2 * b.w;
        o4[3][0] += a3 * b.x; o4[3][1] += a3 * b.y; o4[3][2] += a3 * b.z; o4[3][3] += a3 * b.w;
    }

    float c0 = b2[4 * tc], c1 = b2[4 * tc + 1], c2 = b2[4 * tc + 2], c3 = b2[4 * tc + 3];
#pragma unroll
    for (int i = 0; i < 4; i++) {
        int node = n0 + 4 * tn + i;
        if (node < NN) {
            float* dst = g_h + node * HH + 4 * tc;
            float4 r = make_float4(o4[i][0] + c0, o4[i][1] + c1, o4[i][2] + c2, o4[i][3] + c3);
            if (addm) {
                float4 p = *(const float4*)dst;
                r.x += p.x; r.y += p.y; r.z += p.z; r.w += p.w;
            }
            *(float4*)dst = r;
        }
    }
}

// ---------------- final: relu(LN(h)) @ lin_W + lin_b ----------------
__global__ void k_final(const float* __restrict__ g, const float* __restrict__ b,
                        const float* __restrict__ lw, const float* __restrict__ lb,
                        float* __restrict__ out) {
    int gw = (blockIdx.x * blockDim.x + threadIdx.x) >> 5;
    if (gw >= NN) return;
    int lane = threadIdx.x & 31;
    float2 v = *(const float2*)(g_h + gw * HH + 2 * lane);
    float s = v.x + v.y, sq = v.x * v.x + v.y * v.y;
    for (int o = 16; o; o >>= 1) {
        s  += __shfl_xor_sync(0xffffffffu, s, o);
        sq += __shfl_xor_sync(0xffffffffu, sq, o);
    }
    float mu = s * 0.015625f;
    float var = sq * 0.015625f - mu * mu;
    float rs = rsqrtf(var + 1e-5f);
    float a0 = fmaxf((v.x - mu) * rs * g[2 * lane]     + b[2 * lane],     0.f);
    float a1 = fmaxf((v.y - mu) * rs * g[2 * lane + 1] + b[2 * lane + 1], 0.f);
    float o0 = a0 * lw[(2 * lane) * 3 + 0] + a1 * lw[(2 * lane + 1) * 3 + 0];
    float o1 = a0 * lw[(2 * lane) * 3 + 1] + a1 * lw[(2 * lane + 1) * 3 + 1];
    float o2 = a0 * lw[(2 * lane) * 3 + 2] + a1 * lw[(2 * lane + 1) * 3 + 2];
    for (int w = 16; w; w >>= 1) {
        o0 += __shfl_xor_sync(0xffffffffu, o0, w);
        o1 += __shfl_xor_sync(0xffffffffu, o1, w);
        o2 += __shfl_xor_sync(0xffffffffu, o2, w);
    }
    if (lane == 0) {
        out[gw * 3 + 0] = o0 + lb[0];
        out[gw * 3 + 1] = o1 + lb[1];
        out[gw * 3 + 2] = o2 + lb[2];
    }
}

// ---------------- launch ----------------
extern "C" void kernel_launch(void* const* d_in, const int* in_sizes, int n_in,
                              void* d_out, int out_size) {
    const float* x    = (const float*)d_in[0];
    const int*   ei   = (const int*)  d_in[1];
    const float* encW = (const float*)d_in[2];
    const float* encb = (const float*)d_in[3];
    const float* t    = (const float*)d_in[4];
    const float* W1   = (const float*)d_in[5];
    const float* b1   = (const float*)d_in[6];
    const float* mg   = (const float*)d_in[7];
    const float* mb   = (const float*)d_in[8];
    const float* W2   = (const float*)d_in[9];
    const float* b2   = (const float*)d_in[10];
    const float* lng  = (const float*)d_in[11];
    const float* lnb  = (const float*)d_in[12];
    const float* lw   = (const float*)d_in[13];
    const float* lb   = (const float*)d_in[14];
    float* out = (float*)d_out;

    const int SMEM_MLP = (H2 * 65 + HH * H2 * 2) * 4;  // 98816 bytes
    cudaFuncSetAttribute(k_mlp, cudaFuncAttributeMaxDynamicSharedMemorySize, SMEM_MLP);

    const int NB_SCAN = (NN + 1023) / 1024;  // 98
    const int WARP_BLOCKS = (NN * 32 + 255) / 256;
    const int MLP_BLOCKS  = (NN + 63) / 64;

    // CSR build
    k_zero<<<(NN + 255) / 256, 256>>>();
    k_hist<<<(NE + 255) / 256, 256>>>(ei);
    k_scan_reduce<<<NB_SCAN, 1024>>>();
    k_scan_mid<<<1, 32>>>(NB_SCAN);
    k_scan_final<<<NB_SCAN, 1024>>>();
    k_copy<<<(NN + 255) / 256, 256>>>();
    k_scatter<<<(NE + 255) / 256, 256>>>(ei);

    // encoder -> z
    k_enc<<<(NN * HH + 255) / 256, 256>>>(x, encW, encb);

    // layer 0: h = MLP(LN(agg(z) + z))
    k_agg<<<WARP_BLOCKS, 256>>>(t + 0);
    k_mlp<<<MLP_BLOCKS, 256, SMEM_MLP>>>(W1, b1, mg, mb, W2, b2, 0);

    // layers 1, 2: h = h + genconv(relu(LN_i(h)))
    for (int i = 1; i < 3; i++) {
        k_lnrelu<<<WARP_BLOCKS, 256>>>(lng + i * HH, lnb + i * HH);
        k_agg<<<WARP_BLOCKS, 256>>>(t + i);
        k_mlp<<<MLP_BLOCKS, 256, SMEM_MLP>>>(W1 + i * HH * H2, b1 + i * H2,
                                             mg + i * H2, mb + i * H2,
                                             W2 + i * H2 * HH, b2 + i * HH, 1);
    }

    // final projection
    k_final<<<WARP_BLOCKS, 256>>>(lng, lnb, lw, lb, out);
}

// round 2
// speedup vs baseline: 1.1101x; 1.1101x over previous
#include <cuda_runtime.h>

#define NN 100000
#define NE 1200000
#define HH 64
#define H2 128

// ---------------- device scratch (no allocations allowed) ----------------
__device__ float g_z[NN * HH];   // layer input features
__device__ float g_h[NN * HH];   // residual stream
__device__ float g_u[NN * HH];   // agg + z (MLP input)
__device__ int   g_rowptr[NN + 1];
__device__ int   g_wp[NN];
__device__ int   g_srcs[NE];
__device__ int   g_bsums[128];
__device__ int   g_cnt;

// ---------------- encoder + zero wp + reset counter (launch 0) -----------
__global__ void k_enc_zero(const float* __restrict__ x, const float* __restrict__ W,
                           const float* __restrict__ b) {
    int idx = blockIdx.x * blockDim.x + threadIdx.x;
    if (idx == 0) g_cnt = 0;
    if (idx < NN) g_wp[idx] = 0;
    if (idx >= NN * HH) return;
    int n = idx >> 6, c = idx & 63;
    g_z[idx] = x[n * 3] * W[c] + x[n * 3 + 1] * W[HH + c] + x[n * 3 + 2] * W[2 * HH + c] + b[c];
}

// ---------------- histogram (launch 1) ----------------
__global__ void k_hist(const int* __restrict__ ei) {
    int e = blockIdx.x * blockDim.x + threadIdx.x;
    if (e < NE) atomicAdd(&g_wp[ei[NE + e]], 1);
}

// ------------ per-block reduce + last-block prefix of bsums (launch 2) ----
__global__ void k_reduce_mid(int nb) {
    __shared__ int sd[1024];
    __shared__ int lastf;
    int i = blockIdx.x * 1024 + threadIdx.x;
    sd[threadIdx.x] = (i < NN) ? g_wp[i] : 0;
    __syncthreads();
    for (int s = 512; s > 0; s >>= 1) {
        if ((int)threadIdx.x < s) sd[threadIdx.x] += sd[threadIdx.x + s];
        __syncthreads();
    }
    if (threadIdx.x == 0) {
        g_bsums[blockIdx.x] = sd[0];
        __threadfence();
        int p = atomicAdd(&g_cnt, 1);
        lastf = (p == nb - 1);
    }
    __syncthreads();
    if (lastf && threadIdx.x == 0) {
        int run = 0;
        volatile int* vb = g_bsums;
        for (int bb = 0; bb < nb; bb++) { int t = vb[bb]; vb[bb] = run; run += t; }
        g_rowptr[NN] = run;
    }
}

// ------------ block scan -> exclusive rowptr, also seed wp (launch 3) -----
__global__ void k_scan_final_copy() {
    __shared__ int buf0[1024], buf1[1024];
    int i = blockIdx.x * 1024 + threadIdx.x;
    int x = (i < NN) ? g_wp[i] : 0;
    buf0[threadIdx.x] = x;
    __syncthreads();
    int* cur = buf0; int* nxt = buf1;
    for (int d = 1; d < 1024; d <<= 1) {
        int v = cur[threadIdx.x];
        if ((int)threadIdx.x >= d) v += cur[threadIdx.x - d];
        nxt[threadIdx.x] = v;
        __syncthreads();
        int* tmp = cur; cur = nxt; nxt = tmp;
    }
    if (i < NN) {
        int excl = g_bsums[blockIdx.x] + cur[threadIdx.x] - x;
        g_rowptr[i] = excl;
        g_wp[i] = excl;
    }
}

// ---------------- scatter src ids into CSR (launch 4) ----------------
__global__ void k_scatter(const int* __restrict__ ei) {
    int e = blockIdx.x * blockDim.x + threadIdx.x;
    if (e < NE) {
        int d = ei[NE + e];
        int p = atomicAdd(&g_wp[d], 1);
        g_srcs[p] = ei[e];
    }
}

// ------- single-pass softmax aggregation (warp per node, no max pass) -----
// softmax(l) is shift-invariant; logits here are bounded (~15), so we skip
// the max-subtraction pass entirely. fminf(l,70) is an inert overflow guard.
__global__ void k_agg(const float* __restrict__ tptr) {
    int gw = (blockIdx.x * blockDim.x + threadIdx.x) >> 5;
    if (gw >= NN) return;
    int lane = threadIdx.x & 31;
    int beg = g_rowptr[gw], end = g_rowptr[gw + 1];
    float tt = *tptr;

    float zx = 0.f, zy = 0.f, sx = 0.f, sy = 0.f;
    for (int e = beg; e < end; e++) {
        int s = __ldg(&g_srcs[e]);
        float2 v = *(const float2*)(g_z + s * HH + 2 * lane);
        float ax = fmaxf(v.x, 0.f) + 1e-7f, ay = fmaxf(v.y, 0.f) + 1e-7f;
        float wx = __expf(fminf(ax * tt, 70.f));
        float wy = __expf(fminf(ay * tt, 70.f));
        zx += wx; sx += ax * wx;
        zy += wy; sy += ay * wy;
    }
    float2 zz = *(const float2*)(g_z + gw * HH + 2 * lane);
    float ux = (end > beg) ? sx / zx : 0.f;
    float uy = (end > beg) ? sy / zy : 0.f;
    float2 o = make_float2(ux + zz.x, uy + zz.y);
    *(float2*)(g_u + gw * HH + 2 * lane) = o;
}

// ---------------- outer pre-conv z = relu(LN(h)) ----------------
__global__ void k_lnrelu(const float* __restrict__ g, const float* __restrict__ b) {
    int gw = (blockIdx.x * blockDim.x + threadIdx.x) >> 5;
    if (gw >= NN) return;
    int lane = threadIdx.x & 31;
    float2 v = *(const float2*)(g_h + gw * HH + 2 * lane);
    float s = v.x + v.y, sq = v.x * v.x + v.y * v.y;
    for (int o = 16; o; o >>= 1) {
        s  += __shfl_xor_sync(0xffffffffu, s, o);
        sq += __shfl_xor_sync(0xffffffffu, sq, o);
    }
    float mu = s * 0.015625f;
    float var = sq * 0.015625f - mu * mu;
    float rs = rsqrtf(var + 1e-5f);
    float2 o2;
    o2.x = fmaxf((v.x - mu) * rs * g[2 * lane]     + b[2 * lane],     0.f);
    o2.y = fmaxf((v.y - mu) * rs * g[2 * lane + 1] + b[2 * lane + 1], 0.f);
    *(float2*)(g_z + gw * HH + 2 * lane) = o2;
}

// ---------------- fused MLP: u @ W1 + b1 -> LN -> relu -> @ W2 + b2 -------
extern __shared__ float smem[];
__global__ __launch_bounds__(256, 2) void k_mlp(
    const float* __restrict__ W1, const float* __restrict__ b1,
    const float* __restrict__ gam, const float* __restrict__ bet,
    const float* __restrict__ W2, const float* __restrict__ b2, int addm)
{
    float* sAB = smem;              // reused: sU[64][65] then sHd[128][65]
    float* sW1 = smem + H2 * 65;    // 64*128
    float* sW2 = sW1 + HH * H2;     // 128*64
    int tid = threadIdx.x;
    int n0  = blockIdx.x * 64;

    {
        int w = tid >> 5, l = tid & 31;
        for (int n = w; n < 64; n += 8) {
            int node = n0 + n;
            float2 v = make_float2(0.f, 0.f);
            if (node < NN) v = *(const float2*)(g_u + node * HH + 2 * l);
            sAB[n * 65 + 2 * l]     = v.x;
            sAB[n * 65 + 2 * l + 1] = v.y;
        }
    }
    {
        const float4* s1 = (const float4*)W1; float4* d1 = (float4*)sW1;
        for (int i = tid; i < HH * H2 / 4; i += 256) d1[i] = s1[i];
        const float4* s2 = (const float4*)W2; float4* d2 = (float4*)sW2;
        for (int i = tid; i < HH * H2 / 4; i += 256) d2[i] = s2[i];
    }
    __syncthreads();

    int tc = tid & 15, tn = tid >> 4;

    float acc[4][8];
#pragma unroll
    for (int i = 0; i < 4; i++)
#pragma unroll
        for (int j = 0; j < 8; j++) acc[i][j] = 0.f;

#pragma unroll 8
    for (int k = 0; k < HH; k++) {
        float a0 = sAB[(4 * tn + 0) * 65 + k];
        float a1 = sAB[(4 * tn + 1) * 65 + k];
        float a2 = sAB[(4 * tn + 2) * 65 + k];
        float a3 = sAB[(4 * tn + 3) * 65 + k];
        float4 b0 = *(const float4*)&sW1[k * H2 + 8 * tc];
        float4 bb = *(const float4*)&sW1[k * H2 + 8 * tc + 4];
        float bv[8] = {b0.x, b0.y, b0.z, b0.w, bb.x, bb.y, bb.z, bb.w};
#pragma unroll
        for (int j = 0; j < 8; j++) {
            acc[0][j] += a0 * bv[j];
            acc[1][j] += a1 * bv[j];
            acc[2][j] += a2 * bv[j];
            acc[3][j] += a3 * bv[j];
        }
    }
    __syncthreads();

#pragma unroll
    for (int j = 0; j < 8; j++) {
        float bias = b1[8 * tc + j];
#pragma unroll
        for (int i = 0; i < 4; i++)
            sAB[(8 * tc + j) * 65 + 4 * tn + i] = acc[i][j] + bias;
    }
    __syncthreads();

    {
        int w = tid >> 5, l = tid & 31;
        float g0 = gam[l], g1 = gam[l + 32], g2 = gam[l + 64], g3 = gam[l + 96];
        float e0 = bet[l], e1 = bet[l + 32], e2 = bet[l + 64], e3 = bet[l + 96];
        for (int n = w; n < 64; n += 8) {
            float v0 = sAB[l * 65 + n];
            float v1 = sAB[(l + 32) * 65 + n];
            float v2 = sAB[(l + 64) * 65 + n];
            float v3 = sAB[(l + 96) * 65 + n];
            float s = v0 + v1 + v2 + v3;
            float sq = v0 * v0 + v1 * v1 + v2 * v2 + v3 * v3;
            for (int o = 16; o; o >>= 1) {
                s  += __shfl_xor_sync(0xffffffffu, s, o);
                sq += __shfl_xor_sync(0xffffffffu, sq, o);
            }
            float mu = s * (1.f / 128.f);
            float var = sq * (1.f / 128.f) - mu * mu;
            float rs = rsqrtf(var + 1e-5f);
            sAB[l * 65 + n]        = fmaxf((v0 - mu) * rs * g0 + e0, 0.f);
            sAB[(l + 32) * 65 + n] = fmaxf((v1 - mu) * rs * g1 + e1, 0.f);
            sAB[(l + 64) * 65 + n] = fmaxf((v2 - mu) * rs * g2 + e2, 0.f);
            sAB[(l + 96) * 65 + n] = fmaxf((v3 - mu) * rs * g3 + e3, 0.f);
        }
    }
    __syncthreads();

    float o4[4][4];
#pragma unroll
    for (int i = 0; i < 4; i++)
#pragma unroll
        for (int j = 0; j < 4; j++) o4[i][j] = 0.f;

#pragma unroll 8
    for (int k = 0; k < H2; k++) {
        float a0 = sAB[k * 65 + 4 * tn + 0];
        float a1 = sAB[k * 65 + 4 * tn + 1];
        float a2 = sAB[k * 65 + 4 * tn + 2];
        float a3 = sAB[k * 65 + 4 * tn + 3];
        float4 b = *(const float4*)&sW2[k * HH + 4 * tc];
        o4[0][0] += a0 * b.x; o4[0][1] += a0 * b.y; o4[0][2] += a0 * b.z; o4[0][3] += a0 * b.w;
        o4[1][0] += a1 * b.x; o4[1][1] += a1 * b.y; o4[1][2] += a1 * b.z; o4[1][3] += a1 * b.w;
        o4[2][0] += a2 * b.x; o4[2][1] += a2 * b.y; o4[2][2] += a2 * b.z; o4[2][3] += a2 * b.w;
        o4[3][0] += a3 * b.x; o4[3][1] += a3 * b.y; o4[3][2] += a3 * b.z; o4[3][3] += a3 * b.w;
    }

    float c0 = b2[4 * tc], c1 = b2[4 * tc + 1], c2 = b2[4 * tc + 2], c3 = b2[4 * tc + 3];
#pragma unroll
    for (int i = 0; i < 4; i++) {
        int node = n0 + 4 * tn + i;
        if (node < NN) {
            float* dst = g_h + node * HH + 4 * tc;
            float4 r = make_float4(o4[i][0] + c0, o4[i][1] + c1, o4[i][2] + c2, o4[i][3] + c3);
            if (addm) {
                float4 p = *(const float4*)dst;
                r.x += p.x; r.y += p.y; r.z += p.z; r.w += p.w;
            }
            *(float4*)dst = r;
        }
    }
}

// ---------------- final: relu(LN(h)) @ lin_W + lin_b ----------------
__global__ void k_final(const float* __restrict__ g, const float* __restrict__ b,
                        const float* __restrict__ lw, const float* __restrict__ lb,
                        float* __restrict__ out) {
    int gw = (blockIdx.x * blockDim.x + threadIdx.x) >> 5;
    if (gw >= NN) return;
    int lane = threadIdx.x & 31;
    float2 v = *(const float2*)(g_h + gw * HH + 2 * lane);
    float s = v.x + v.y, sq = v.x * v.x + v.y * v.y;
    for (int o = 16; o; o >>= 1) {
        s  += __shfl_xor_sync(0xffffffffu, s, o);
        sq += __shfl_xor_sync(0xffffffffu, sq, o);
    }
    float mu = s * 0.015625f;
    float var = sq * 0.015625f - mu * mu;
    float rs = rsqrtf(var + 1e-5f);
    float a0 = fmaxf((v.x - mu) * rs * g[2 * lane]     + b[2 * lane],     0.f);
    float a1 = fmaxf((v.y - mu) * rs * g[2 * lane + 1] + b[2 * lane + 1], 0.f);
    float o0 = a0 * lw[(2 * lane) * 3 + 0] + a1 * lw[(2 * lane + 1) * 3 + 0];
    float o1 = a0 * lw[(2 * lane) * 3 + 1] + a1 * lw[(2 * lane + 1) * 3 + 1];
    float o2 = a0 * lw[(2 * lane) * 3 + 2] + a1 * lw[(2 * lane + 1) * 3 + 2];
    for (int w = 16; w; w >>= 1) {
        o0 += __shfl_xor_sync(0xffffffffu, o0, w);
        o1 += __shfl_xor_sync(0xffffffffu, o1, w);
        o2 += __shfl_xor_sync(0xffffffffu, o2, w);
    }
    if (lane == 0) {
        out[gw * 3 + 0] = o0 + lb[0];
        out[gw * 3 + 1] = o1 + lb[1];
        out[gw * 3 + 2] = o2 + lb[2];
    }
}

// ---------------- launch ----------------
extern "C" void kernel_launch(void* const* d_in, const int* in_sizes, int n_in,
                              void* d_out, int out_size) {
    const float* x    = (const float*)d_in[0];
    const int*   ei   = (const int*)  d_in[1];
    const float* encW = (const float*)d_in[2];
    const float* encb = (const float*)d_in[3];
    const float* t    = (const float*)d_in[4];
    const float* W1   = (const float*)d_in[5];
    const float* b1   = (const float*)d_in[6];
    const float* mg   = (const float*)d_in[7];
    const float* mb   = (const float*)d_in[8];
    const float* W2   = (const float*)d_in[9];
    const float* b2   = (const float*)d_in[10];
    const float* lng  = (const float*)d_in[11];
    const float* lnb  = (const float*)d_in[12];
    const float* lw   = (const float*)d_in[13];
    const float* lb   = (const float*)d_in[14];
    float* out = (float*)d_out;

    const int SMEM_MLP = (H2 * 65 + HH * H2 * 2) * 4;  // 98816 bytes
    cudaFuncSetAttribute(k_mlp, cudaFuncAttributeMaxDynamicSharedMemorySize, SMEM_MLP);

    const int NB_SCAN = (NN + 1023) / 1024;  // 98
    const int WARP_BLOCKS = (NN * 32 + 255) / 256;
    const int MLP_BLOCKS  = (NN + 63) / 64;

    // CSR build (5 launches: 0..4)
    k_enc_zero<<<(NN * HH + 255) / 256, 256>>>(x, encW, encb);
    k_hist<<<(NE + 255) / 256, 256>>>(ei);
    k_reduce_mid<<<NB_SCAN, 1024>>>(NB_SCAN);
    k_scan_final_copy<<<NB_SCAN, 1024>>>();
    k_scatter<<<(NE + 255) / 256, 256>>>(ei);

    // layer 0 (launch 5 = k_agg -> gets the ncu profile slot)
    k_agg<<<WARP_BLOCKS, 256>>>(t + 0);
    k_mlp<<<MLP_BLOCKS, 256, SMEM_MLP>>>(W1, b1, mg, mb, W2, b2, 0);

    // layers 1, 2
    for (int i = 1; i < 3; i++) {
        k_lnrelu<<<WARP_BLOCKS, 256>>>(lng + i * HH, lnb + i * HH);
        k_agg<<<WARP_BLOCKS, 256>>>(t + i);
        k_mlp<<<MLP_BLOCKS, 256, SMEM_MLP>>>(W1 + i * HH * H2, b1 + i * H2,
                                             mg + i * H2, mb + i * H2,
                                             W2 + i * H2 * HH, b2 + i * HH, 1);
    }

    // final projection
    k_final<<<WARP_BLOCKS, 256>>>(lng, lnb, lw, lb, out);
}

// round 3
// speedup vs baseline: 1.1438x; 1.0303x over previous
#include <cuda_runtime.h>

#define NN 100000
#define NE 1200000
#define HH 64
#define H2 128
#define NB_SCAN 98

// ---------------- device scratch (no allocations allowed) ----------------
__device__ float g_z[NN * HH];   // layer input features
__device__ float g_h[NN * HH];   // residual stream
__device__ float g_u[NN * HH];   // agg + z (MLP input)
__device__ int   g_rowptr[NN + 1];
__device__ int   g_wp[NN];       // zeroed by previous replay's k_final
__device__ int   g_srcs[NE];
__device__ int   g_sval[128];    // lookback aggregates
__device__ int   g_sincl[128];   // lookback inclusive prefixes
__device__ int   g_sflag[128];   // 0=empty 1=aggregate 2=inclusive (tail-zeroed)

// ---------------- f32x2 packed-FMA helpers ----------------
__device__ __forceinline__ unsigned long long pk2dup(float x) {
    unsigned long long r;
    asm("mov.b64 %0, {%1, %1};" : "=l"(r) : "f"(x));
    return r;
}
__device__ __forceinline__ void fma2(unsigned long long& c, unsigned long long a,
                                     unsigned long long b) {
    asm("fma.rn.f32x2 %0, %1, %2, %0;" : "+l"(c) : "l"(a), "l"(b));
}
__device__ __forceinline__ float2 upk(unsigned long long v) {
    float2 f;
    asm("mov.b64 {%0, %1}, %2;" : "=f"(f.x), "=f"(f.y) : "l"(v));
    return f;
}

// ------------- launch 0: encoder + degree histogram -------------
__global__ void k_enc_hist(const float* __restrict__ x, const float* __restrict__ W,
                           const float* __restrict__ b, const int* __restrict__ ei) {
    int idx = blockIdx.x * blockDim.x + threadIdx.x;
    if (idx == 0) g_rowptr[NN] = NE;
    if (idx < NE) atomicAdd(&g_wp[ei[NE + idx]], 1);
    if (idx < NN * HH) {
        int n = idx >> 6, c = idx & 63;
        g_z[idx] = x[n * 3] * W[c] + x[n * 3 + 1] * W[HH + c]
                 + x[n * 3 + 2] * W[2 * HH + c] + b[c];
    }
}

// ------------- launch 1: single-pass scan (decoupled lookback) -------------
__global__ void k_scan() {
    __shared__ int wsum[32];
    __shared__ int s_excl;
    int t = threadIdx.x, b = blockIdx.x;
    int lane = t & 31, wid = t >> 5;
    int i = b * 1024 + t;
    int x = (i < NN) ? g_wp[i] : 0;

    // warp inclusive scan
    int v = x;
#pragma unroll
    for (int d = 1; d < 32; d <<= 1) {
        int u = __shfl_up_sync(0xffffffffu, v, d);
        if (lane >= d) v += u;
    }
    if (lane == 31) wsum[wid] = v;
    __syncthreads();
    if (wid == 0) {
        int w = wsum[lane];
#pragma unroll
        for (int d = 1; d < 32; d <<= 1) {
            int u = __shfl_up_sync(0xffffffffu, w, d);
            if (lane >= d) w += u;
        }
        wsum[lane] = w;
    }
    __syncthreads();
    int incl = v + (wid ? wsum[wid - 1] : 0);
    int bsum = wsum[31];

    if (t == 0) {
        if (b == 0) {
            g_sincl[0] = bsum; __threadfence(); g_sflag[0] = 2;
            s_excl = 0;
        } else {
            g_sval[b] = bsum; __threadfence(); g_sflag[b] = 1;
            int excl = 0, j = b - 1;
            while (true) {
                int f;
                do { f = ((volatile int*)g_sflag)[j]; } while (f == 0);
                __threadfence();
                if (f == 2) { excl += ((volatile int*)g_sincl)[j]; break; }
                excl += ((volatile int*)g_sval)[j]; j--;
            }
            g_sincl[b] = excl + bsum; __threadfence(); g_sflag[b] = 2;
            s_excl = excl;
        }
    }
    __syncthreads();
    if (i < NN) {
        int e = s_excl + incl - x;
        g_rowptr[i] = e;
        g_wp[i] = e;
    }
}

// ------------- launch 2: scatter src ids into CSR -------------
__global__ void k_scatter(const int* __restrict__ ei) {
    int e = blockIdx.x * blockDim.x + threadIdx.x;
    if (e < NE) {
        int d = ei[NE + e];
        int p = atomicAdd(&g_wp[d], 1);
        g_srcs[p] = ei[e];
    }
}

// ------- single-pass softmax aggregation (warp per node, batched idx) -----
__global__ void k_agg(const float* __restrict__ tptr) {
    int gw = (blockIdx.x * blockDim.x + threadIdx.x) >> 5;
    if (gw >= NN) return;
    int lane = threadIdx.x & 31;
    int beg = g_rowptr[gw], end = g_rowptr[gw + 1];
    float tt = *tptr;

    float zx = 0.f, zy = 0.f, sx = 0.f, sy = 0.f;
    for (int base = beg; base < end; base += 32) {
        int n = end - base; if (n > 32) n = 32;
        int sid = (base + lane < end) ? __ldg(&g_srcs[base + lane]) : 0;
#pragma unroll 4
        for (int j = 0; j < n; j++) {
            int s = __shfl_sync(0xffffffffu, sid, j);
            float2 v = *(const float2*)(g_z + s * HH + 2 * lane);
            float ax = fmaxf(v.x, 0.f) + 1e-7f, ay = fmaxf(v.y, 0.f) + 1e-7f;
            float wx = __expf(fminf(ax * tt, 70.f));
            float wy = __expf(fminf(ay * tt, 70.f));
            zx += wx; sx += ax * wx;
            zy += wy; sy += ay * wy;
        }
    }
    float2 zz = *(const float2*)(g_z + gw * HH + 2 * lane);
    float ux = (end > beg) ? sx / zx : 0.f;
    float uy = (end > beg) ? sy / zy : 0.f;
    float2 o = make_float2(ux + zz.x, uy + zz.y);
    *(float2*)(g_u + gw * HH + 2 * lane) = o;
}

// ---------------- outer pre-conv z = relu(LN(h)) ----------------
__global__ void k_lnrelu(const float* __restrict__ g, const float* __restrict__ b) {
    int gw = (blockIdx.x * blockDim.x + threadIdx.x) >> 5;
    if (gw >= NN) return;
    int lane = threadIdx.x & 31;
    float2 v = *(const float2*)(g_h + gw * HH + 2 * lane);
    float s = v.x + v.y, sq = v.x * v.x + v.y * v.y;
    for (int o = 16; o; o >>= 1) {
        s  += __shfl_xor_sync(0xffffffffu, s, o);
        sq += __shfl_xor_sync(0xffffffffu, sq, o);
    }
    float mu = s * 0.015625f;
    float var = sq * 0.015625f - mu * mu;
    float rs = rsqrtf(var + 1e-5f);
    float2 o2;
    o2.x = fmaxf((v.x - mu) * rs * g[2 * lane]     + b[2 * lane],     0.f);
    o2.y = fmaxf((v.y - mu) * rs * g[2 * lane + 1] + b[2 * lane + 1], 0.f);
    *(float2*)(g_z + gw * HH + 2 * lane) = o2;
}

// -------- fused MLP with packed f32x2 FMAs --------
extern __shared__ float smem[];
__global__ __launch_bounds__(256, 2) void k_mlp(
    const float* __restrict__ W1, const float* __restrict__ b1,
    const float* __restrict__ gam, const float* __restrict__ bet,
    const float* __restrict__ W2, const float* __restrict__ b2, int addm)
{
    float* sAB = smem;              // reused: sU[64][65] then sHd[128][65]
    float* sW1 = smem + H2 * 65;    // 64*128
    float* sW2 = sW1 + HH * H2;     // 128*64
    int tid = threadIdx.x;
    int n0  = blockIdx.x * 64;

    {
        int w = tid >> 5, l = tid & 31;
        for (int n = w; n < 64; n += 8) {
            int node = n0 + n;
            float2 v = make_float2(0.f, 0.f);
            if (node < NN) v = *(const float2*)(g_u + node * HH + 2 * l);
            sAB[n * 65 + 2 * l]     = v.x;
            sAB[n * 65 + 2 * l + 1] = v.y;
        }
    }
    {
        const float4* s1 = (const float4*)W1; float4* d1 = (float4*)sW1;
        for (int i = tid; i < HH * H2 / 4; i += 256) d1[i] = s1[i];
        const float4* s2 = (const float4*)W2; float4* d2 = (float4*)sW2;
        for (int i = tid; i < HH * H2 / 4; i += 256) d2[i] = s2[i];
    }
    __syncthreads();

    int tc = tid & 15, tn = tid >> 4;

    // GEMM1: 4 nodes x 8 ch per thread, packed pairs over ch
    unsigned long long acc[4][4];
#pragma unroll
    for (int i = 0; i < 4; i++)
#pragma unroll
        for (int j = 0; j < 4; j++) acc[i][j] = 0ull;

#pragma unroll 8
    for (int k = 0; k < HH; k++) {
        unsigned long long p0 = pk2dup(sAB[(4 * tn + 0) * 65 + k]);
        unsigned long long p1 = pk2dup(sAB[(4 * tn + 1) * 65 + k]);
        unsigned long long p2 = pk2dup(sAB[(4 * tn + 2) * 65 + k]);
        unsigned long long p3 = pk2dup(sAB[(4 * tn + 3) * 65 + k]);
        const unsigned long long* br = (const unsigned long long*)&sW1[k * H2 + 8 * tc];
        unsigned long long b0 = br[0], b1v = br[1], b2v = br[2], b3v = br[3];
        fma2(acc[0][0], p0, b0); fma2(acc[0][1], p0, b1v); fma2(acc[0][2], p0, b2v); fma2(acc[0][3], p0, b3v);
        fma2(acc[1][0], p1, b0); fma2(acc[1][1], p1, b1v); fma2(acc[1][2], p1, b2v); fma2(acc[1][3], p1, b3v);
        fma2(acc[2][0], p2, b0); fma2(acc[2][1], p2, b1v); fma2(acc[2][2], p2, b2v); fma2(acc[2][3], p2, b3v);
        fma2(acc[3][0], p3, b0); fma2(acc[3][1], p3, b1v); fma2(acc[3][2], p3, b2v); fma2(acc[3][3], p3, b3v);
    }
    __syncthreads();

    // stash hidden transposed + bias
#pragma unroll
    for (int jp = 0; jp < 4; jp++) {
        float2 bb = *(const float2*)&b1[8 * tc + 2 * jp];
#pragma unroll
        for (int i = 0; i < 4; i++) {
            float2 v = upk(acc[i][jp]);
            sAB[(8 * tc + 2 * jp)     * 65 + 4 * tn + i] = v.x + bb.x;
            sAB[(8 * tc + 2 * jp + 1) * 65 + 4 * tn + i] = v.y + bb.y;
        }
    }
    __syncthreads();

    // LayerNorm(128) + relu in-place
    {
        int w = tid >> 5, l = tid & 31;
        float g0 = gam[l], g1 = gam[l + 32], g2 = gam[l + 64], g3 = gam[l + 96];
        float e0 = bet[l], e1 = bet[l + 32], e2 = bet[l + 64], e3 = bet[l + 96];
        for (int n = w; n < 64; n += 8) {
            float v0 = sAB[l * 65 + n];
            float v1 = sAB[(l + 32) * 65 + n];
            float v2 = sAB[(l + 64) * 65 + n];
            float v3 = sAB[(l + 96) * 65 + n];
            float s = v0 + v1 + v2 + v3;
            float sq = v0 * v0 + v1 * v1 + v2 * v2 + v3 * v3;
            for (int o = 16; o; o >>= 1) {
                s  += __shfl_xor_sync(0xffffffffu, s, o);
                sq += __shfl_xor_sync(0xffffffffu, sq, o);
            }
            float mu = s * (1.f / 128.f);
            float var = sq * (1.f / 128.f) - mu * mu;
            float rs = rsqrtf(var + 1e-5f);
            sAB[l * 65 + n]        = fmaxf((v0 - mu) * rs * g0 + e0, 0.f);
            sAB[(l + 32) * 65 + n] = fmaxf((v1 - mu) * rs * g1 + e1, 0.f);
            sAB[(l + 64) * 65 + n] = fmaxf((v2 - mu) * rs * g2 + e2, 0.f);
            sAB[(l + 96) * 65 + n] = fmaxf((v3 - mu) * rs * g3 + e3, 0.f);
        }
    }
    __syncthreads();

    // GEMM2: 4 nodes x 4 ch, packed pairs over ch
    unsigned long long o2[4][2];
#pragma unroll
    for (int i = 0; i < 4; i++) { o2[i][0] = 0ull; o2[i][1] = 0ull; }

#pragma unroll 8
    for (int k = 0; k < H2; k++) {
        unsigned long long p0 = pk2dup(sAB[k * 65 + 4 * tn + 0]);
        unsigned long long p1 = pk2dup(sAB[k * 65 + 4 * tn + 1]);
        unsigned long long p2 = pk2dup(sAB[k * 65 + 4 * tn + 2]);
        unsigned long long p3 = pk2dup(sAB[k * 65 + 4 * tn + 3]);
        const unsigned long long* br = (const unsigned long long*)&sW2[k * HH + 4 * tc];
        unsigned long long b0 = br[0], b1v = br[1];
        fma2(o2[0][0], p0, b0); fma2(o2[0][1], p0, b1v);
        fma2(o2[1][0], p1, b0); fma2(o2[1][1], p1, b1v);
        fma2(o2[2][0], p2, b0); fma2(o2[2][1], p2, b1v);
        fma2(o2[3][0], p3, b0); fma2(o2[3][1], p3, b1v);
    }

    float c0 = b2[4 * tc], c1 = b2[4 * tc + 1], c2 = b2[4 * tc + 2], c3 = b2[4 * tc + 3];
#pragma unroll
    for (int i = 0; i < 4; i++) {
        int node = n0 + 4 * tn + i;
        if (node < NN) {
            float* dst = g_h + node * HH + 4 * tc;
            float2 lo = upk(o2[i][0]), hi = upk(o2[i][1]);
            float4 r = make_float4(lo.x + c0, lo.y + c1, hi.x + c2, hi.y + c3);
            if (addm) {
                float4 p = *(const float4*)dst;
                r.x += p.x; r.y += p.y; r.z += p.z; r.w += p.w;
            }
            *(float4*)dst = r;
        }
    }
}

// -------- final: relu(LN(h)) @ lin_W + lin_b ; also re-zero scratch --------
__global__ void k_final(const float* __restrict__ g, const float* __restrict__ b,
                        const float* __restrict__ lw, const float* __restrict__ lb,
                        float* __restrict__ out) {
    int gw = (blockIdx.x * blockDim.x + threadIdx.x) >> 5;
    if (gw >= NN) return;
    int lane = threadIdx.x & 31;
    // zero scratch for next graph replay (g_wp, lookback flags)
    if (lane == 1) g_wp[gw] = 0;
    if (gw < 128 && lane == 2) g_sflag[gw] = 0;

    float2 v = *(const float2*)(g_h + gw * HH + 2 * lane);
    float s = v.x + v.y, sq = v.x * v.x + v.y * v.y;
    for (int o = 16; o; o >>= 1) {
        s  += __shfl_xor_sync(0xffffffffu, s, o);
        sq += __shfl_xor_sync(0xffffffffu, sq, o);
    }
    float mu = s * 0.015625f;
    float var = sq * 0.015625f - mu * mu;
    float rs = rsqrtf(var + 1e-5f);
    float a0 = fmaxf((v.x - mu) * rs * g[2 * lane]     + b[2 * lane],     0.f);
    float a1 = fmaxf((v.y - mu) * rs * g[2 * lane + 1] + b[2 * lane + 1], 0.f);
    float o0 = a0 * lw[(2 * lane) * 3 + 0] + a1 * lw[(2 * lane + 1) * 3 + 0];
    float o1 = a0 * lw[(2 * lane) * 3 + 1] + a1 * lw[(2 * lane + 1) * 3 + 1];
    float o2 = a0 * lw[(2 * lane) * 3 + 2] + a1 * lw[(2 * lane + 1) * 3 + 2];
    for (int w = 16; w; w >>= 1) {
        o0 += __shfl_xor_sync(0xffffffffu, o0, w);
        o1 += __shfl_xor_sync(0xffffffffu, o1, w);
        o2 += __shfl_xor_sync(0xffffffffu, o2, w);
    }
    if (lane == 0) {
        out[gw * 3 + 0] = o0 + lb[0];
        out[gw * 3 + 1] = o1 + lb[1];
        out[gw * 3 + 2] = o2 + lb[2];
    }
}

// ---------------- launch ----------------
extern "C" void kernel_launch(void* const* d_in, const int* in_sizes, int n_in,
                              void* d_out, int out_size) {
    const float* x    = (const float*)d_in[0];
    const int*   ei   = (const int*)  d_in[1];
    const float* encW = (const float*)d_in[2];
    const float* encb = (const float*)d_in[3];
    const float* t    = (const float*)d_in[4];
    const float* W1   = (const float*)d_in[5];
    const float* b1   = (const float*)d_in[6];
    const float* mg   = (const float*)d_in[7];
    const float* mb   = (const float*)d_in[8];
    const float* W2   = (const float*)d_in[9];
    const float* b2   = (const float*)d_in[10];
    const float* lng  = (const float*)d_in[11];
    const float* lnb  = (const float*)d_in[12];
    const float* lw   = (const float*)d_in[13];
    const float* lb   = (const float*)d_in[14];
    float* out = (float*)d_out;

    const int SMEM_MLP = (H2 * 65 + HH * H2 * 2) * 4;  // 98816 bytes
    cudaFuncSetAttribute(k_mlp, cudaFuncAttributeMaxDynamicSharedMemorySize, SMEM_MLP);

    const int WARP_BLOCKS = (NN * 32 + 255) / 256;
    const int MLP_BLOCKS  = (NN + 63) / 64;

    // CSR build (launches 0..2)
    k_enc_hist<<<(NN * HH + 255) / 256, 256>>>(x, encW, encb, ei);
    k_scan<<<NB_SCAN, 1024>>>();
    k_scatter<<<(NE + 255) / 256, 256>>>(ei);

    // layer 0 (launch 3 = k_agg -> profiled slot)
    k_agg<<<WARP_BLOCKS, 256>>>(t + 0);
    k_mlp<<<MLP_BLOCKS, 256, SMEM_MLP>>>(W1, b1, mg, mb, W2, b2, 0);

    // layers 1, 2
    for (int i = 1; i < 3; i++) {
        k_lnrelu<<<WARP_BLOCKS, 256>>>(lng + i * HH, lnb + i * HH);
        k_agg<<<WARP_BLOCKS, 256>>>(t + i);
        k_mlp<<<MLP_BLOCKS, 256, SMEM_MLP>>>(W1 + i * HH * H2, b1 + i * H2,
                                             mg + i * H2, mb + i * H2,
                                             W2 + i * H2 * HH, b2 + i * HH, 1);
    }

    // final projection (+ scratch re-zero for next replay)
    k_final<<<WARP_BLOCKS, 256>>>(lng, lnb, lw, lb, out);
}

// round 4
// speedup vs baseline: 1.2769x; 1.1164x over previous
#include <cuda_runtime.h>

#define NN 100000
#define NE 1200000
#define HH 64
#define H2 128
#define NB_SCAN 98

// ---------------- device scratch (no allocations allowed) ----------------
__device__ float g_z[NN * HH];   // layer input features
__device__ float g_h[NN * HH];   // residual stream
__device__ float g_u[NN * HH];   // agg + z (MLP input)
__device__ int   g_rowptr[NN + 1];
__device__ int   g_wp[NN];       // zeroed by previous replay's k_final
__device__ int   g_srcs[NE];
__device__ int   g_sval[128];    // lookback aggregates
__device__ int   g_sincl[128];   // lookback inclusive prefixes
__device__ int   g_sflag[128];   // 0=empty 1=aggregate 2=inclusive (tail-zeroed)

// ---------------- tf32 helpers ----------------
__device__ __forceinline__ unsigned cvt_tf32(float x) {
    unsigned r; asm("cvt.rna.tf32.f32 %0, %1;" : "=r"(r) : "f"(x)); return r;
}
__device__ __forceinline__ void split2(float x, unsigned& h, unsigned& l) {
    h = cvt_tf32(x);
    l = cvt_tf32(x - __uint_as_float(h));
}
__device__ __forceinline__ void mma8(float* c, unsigned a0, unsigned a1,
                                     unsigned a2, unsigned a3,
                                     unsigned b0, unsigned b1) {
    asm("mma.sync.aligned.m16n8k8.row.col.f32.tf32.tf32.f32 "
        "{%0,%1,%2,%3}, {%4,%5,%6,%7}, {%8,%9}, {%0,%1,%2,%3};"
        : "+f"(c[0]), "+f"(c[1]), "+f"(c[2]), "+f"(c[3])
        : "r"(a0), "r"(a1), "r"(a2), "r"(a3), "r"(b0), "r"(b1));
}
__device__ __forceinline__ float ex2(float x) {
    float r; asm("ex2.approx.f32 %0, %1;" : "=f"(r) : "f"(x)); return r;
}

// ------------- launch 0: encoder + degree histogram -------------
__global__ void k_enc_hist(const float* __restrict__ x, const float* __restrict__ W,
                           const float* __restrict__ b, const int* __restrict__ ei) {
    int idx = blockIdx.x * blockDim.x + threadIdx.x;
    if (idx == 0) g_rowptr[NN] = NE;
    if (idx < NE) atomicAdd(&g_wp[ei[NE + idx]], 1);
    if (idx < NN * HH) {
        int n = idx >> 6, c = idx & 63;
        g_z[idx] = x[n * 3] * W[c] + x[n * 3 + 1] * W[HH + c]
                 + x[n * 3 + 2] * W[2 * HH + c] + b[c];
    }
}

// ------------- launch 1: single-pass scan (decoupled lookback) -------------
__global__ void k_scan() {
    __shared__ int wsum[32];
    __shared__ int s_excl;
    int t = threadIdx.x, b = blockIdx.x;
    int lane = t & 31, wid = t >> 5;
    int i = b * 1024 + t;
    int x = (i < NN) ? g_wp[i] : 0;

    int v = x;
#pragma unroll
    for (int d = 1; d < 32; d <<= 1) {
        int u = __shfl_up_sync(0xffffffffu, v, d);
        if (lane >= d) v += u;
    }
    if (lane == 31) wsum[wid] = v;
    __syncthreads();
    if (wid == 0) {
        int w = wsum[lane];
#pragma unroll
        for (int d = 1; d < 32; d <<= 1) {
            int u = __shfl_up_sync(0xffffffffu, w, d);
            if (lane >= d) w += u;
        }
        wsum[lane] = w;
    }
    __syncthreads();
    int incl = v + (wid ? wsum[wid - 1] : 0);
    int bsum = wsum[31];

    if (t == 0) {
        if (b == 0) {
            g_sincl[0] = bsum; __threadfence(); g_sflag[0] = 2;
            s_excl = 0;
        } else {
            g_sval[b] = bsum; __threadfence(); g_sflag[b] = 1;
            int excl = 0, j = b - 1;
            while (true) {
                int f;
                do { f = ((volatile int*)g_sflag)[j]; } while (f == 0);
                __threadfence();
                if (f == 2) { excl += ((volatile int*)g_sincl)[j]; break; }
                excl += ((volatile int*)g_sval)[j]; j--;
            }
            g_sincl[b] = excl + bsum; __threadfence(); g_sflag[b] = 2;
            s_excl = excl;
        }
    }
    __syncthreads();
    if (i < NN) {
        int e = s_excl + incl - x;
        g_rowptr[i] = e;
        g_wp[i] = e;
    }
}

// ------------- launch 2: scatter src ids into CSR -------------
__global__ void k_scatter(const int* __restrict__ ei) {
    int e = blockIdx.x * blockDim.x + threadIdx.x;
    if (e < NE) {
        int d = ei[NE + e];
        int p = atomicAdd(&g_wp[d], 1);
        g_srcs[p] = ei[e];
    }
}

// ------- single-pass softmax aggregation: warp/node, 2 edges per step -----
__global__ void k_agg(const float* __restrict__ tptr) {
    int gw = (blockIdx.x * blockDim.x + threadIdx.x) >> 5;
    if (gw >= NN) return;
    int lane = threadIdx.x & 31;
    int half = lane >> 4, sl = lane & 15;
    int beg = g_rowptr[gw], end = g_rowptr[gw + 1];
    float tt = __ldg(tptr);
    float tl2 = tt * 1.44269504f;          // t * log2(e)
    float eoff = 1e-7f * tl2;              // eps * t * log2(e)

    float z0 = 0.f, z1 = 0.f, z2 = 0.f, z3 = 0.f;
    float s0 = 0.f, s1 = 0.f, s2 = 0.f, s3 = 0.f;

    for (int base = beg; base < end; base += 32) {
        int nn = end - base; if (nn > 32) nn = 32;
        int sid = (base + lane < end) ? __ldg(&g_srcs[base + lane]) : 0;
        int j = 0;
#pragma unroll 2
        for (; j + 2 <= nn; j += 2) {
            int s = __shfl_sync(0xffffffffu, sid, j + half);
            float4 v = *(const float4*)(g_z + s * HH + 4 * sl);
            float r0 = fmaxf(v.x, 0.f), r1 = fmaxf(v.y, 0.f);
            float r2 = fmaxf(v.z, 0.f), r3 = fmaxf(v.w, 0.f);
            float w0 = ex2(fmaf(r0, tl2, eoff));
            float w1 = ex2(fmaf(r1, tl2, eoff));
            float w2 = ex2(fmaf(r2, tl2, eoff));
            float w3 = ex2(fmaf(r3, tl2, eoff));
            z0 += w0; z1 += w1; z2 += w2; z3 += w3;
            s0 = fmaf(r0 + 1e-7f, w0, s0);
            s1 = fmaf(r1 + 1e-7f, w1, s1);
            s2 = fmaf(r2 + 1e-7f, w2, s2);
            s3 = fmaf(r3 + 1e-7f, w3, s3);
        }
        if (j < nn) {
            int s = __shfl_sync(0xffffffffu, sid, j);
            if (half == 0) {
                float4 v = *(const float4*)(g_z + s * HH + 4 * sl);
                float r0 = fmaxf(v.x, 0.f), r1 = fmaxf(v.y, 0.f);
                float r2 = fmaxf(v.z, 0.f), r3 = fmaxf(v.w, 0.f);
                float w0 = ex2(fmaf(r0, tl2, eoff));
                float w1 = ex2(fmaf(r1, tl2, eoff));
                float w2 = ex2(fmaf(r2, tl2, eoff));
                float w3 = ex2(fmaf(r3, tl2, eoff));
                z0 += w0; z1 += w1; z2 += w2; z3 += w3;
                s0 = fmaf(r0 + 1e-7f, w0, s0);
                s1 = fmaf(r1 + 1e-7f, w1, s1);
                s2 = fmaf(r2 + 1e-7f, w2, s2);
                s3 = fmaf(r3 + 1e-7f, w3, s3);
            }
        }
    }
    // combine the two edge-halves (channel c lives in lanes sl and sl+16)
    z0 += __shfl_xor_sync(0xffffffffu, z0, 16);
    z1 += __shfl_xor_sync(0xffffffffu, z1, 16);
    z2 += __shfl_xor_sync(0xffffffffu, z2, 16);
    z3 += __shfl_xor_sync(0xffffffffu, z3, 16);
    s0 += __shfl_xor_sync(0xffffffffu, s0, 16);
    s1 += __shfl_xor_sync(0xffffffffu, s1, 16);
    s2 += __shfl_xor_sync(0xffffffffu, s2, 16);
    s3 += __shfl_xor_sync(0xffffffffu, s3, 16);

    if (half == 0) {
        float4 zz = *(const float4*)(g_z + gw * HH + 4 * sl);
        float4 o;
        if (end > beg) {
            o.x = __fdividef(s0, z0) + zz.x;
            o.y = __fdividef(s1, z1) + zz.y;
            o.z = __fdividef(s2, z2) + zz.z;
            o.w = __fdividef(s3, z3) + zz.w;
        } else {
            o = zz;
        }
        *(float4*)(g_u + gw * HH + 4 * sl) = o;
    }
}

// ---------------- outer pre-conv z = relu(LN(h)) ----------------
__global__ void k_lnrelu(const float* __restrict__ g, const float* __restrict__ b) {
    int gw = (blockIdx.x * blockDim.x + threadIdx.x) >> 5;
    if (gw >= NN) return;
    int lane = threadIdx.x & 31;
    float2 v = *(const float2*)(g_h + gw * HH + 2 * lane);
    float s = v.x + v.y, sq = v.x * v.x + v.y * v.y;
    for (int o = 16; o; o >>= 1) {
        s  += __shfl_xor_sync(0xffffffffu, s, o);
        sq += __shfl_xor_sync(0xffffffffu, sq, o);
    }
    float mu = s * 0.015625f;
    float var = sq * 0.015625f - mu * mu;
    float rs = rsqrtf(var + 1e-5f);
    float2 o2;
    o2.x = fmaxf((v.x - mu) * rs * g[2 * lane]     + b[2 * lane],     0.f);
    o2.y = fmaxf((v.y - mu) * rs * g[2 * lane + 1] + b[2 * lane + 1], 0.f);
    *(float2*)(g_z + gw * HH + 2 * lane) = o2;
}

// -------- fused MLP on tensor cores: tf32 mma with 3xTF32 split ----------
// block = 64 nodes, 256 threads (8 warps). smem (floats):
//   [0      .. 8704)  sUH[64][68] + sUL[64][68]  -> later sHid[64][132]
//   [8704   .. 17408) sW1 fp32 [64][136]
//   [17408  .. 26624) sW2 fp32 [128][72]
extern __shared__ float sm_mlp[];
__global__ __launch_bounds__(256, 2) void k_mlp(
    const float* __restrict__ W1g, const float* __restrict__ b1g,
    const float* __restrict__ gamg, const float* __restrict__ betg,
    const float* __restrict__ W2g, const float* __restrict__ b2g, int addm)
{
    float* sm = sm_mlp;
    unsigned* sUH = (unsigned*)sm;            // [64][68]
    unsigned* sUL = (unsigned*)sm + 64 * 68;  // [64][68]
    float*    sHid = sm;                      // [64][132], aliases sU after GEMM1
    float*    sW1  = sm + 8704;               // [64][136]
    float*    sW2  = sm + 17408;              // [128][72]

    int tid = threadIdx.x;
    int n0 = blockIdx.x * 64;
    int w = tid >> 5, lane = tid & 31;
    int gq = lane >> 2, t4 = lane & 3;
    int wm = w & 3, wn = w >> 2;

    // ---- fill U (pre-split hi/lo) ----
    for (int idx = tid; idx < 64 * 32; idx += 256) {
        int r = idx >> 5, c = (idx & 31) * 2;
        int node = n0 + r;
        float2 v = make_float2(0.f, 0.f);
        if (node < NN) v = *(const float2*)(g_u + node * HH + c);
        unsigned h0, l0, h1, l1;
        split2(v.x, h0, l0);
        split2(v.y, h1, l1);
        sUH[r * 68 + c] = h0; sUH[r * 68 + c + 1] = h1;
        sUL[r * 68 + c] = l0; sUL[r * 68 + c + 1] = l1;
    }
    // ---- fill weights (fp32) ----
    for (int i = tid; i < 64 * 128; i += 256)
        sW1[(i >> 7) * 136 + (i & 127)] = W1g[i];
    for (int i = tid; i < 128 * 64; i += 256)
        sW2[(i >> 6) * 72 + (i & 63)] = W2g[i];
    __syncthreads();

    // ---- GEMM1: hid[64][128] = U[64][64] @ W1[64][128] ----
    float c1[8][4];
#pragma unroll
    for (int j = 0; j < 8; j++)
#pragma unroll
        for (int q = 0; q < 4; q++) c1[j][q] = 0.f;

    int ar0 = (16 * wm + gq) * 68, ar1 = ar0 + 8 * 68;
#pragma unroll
    for (int ks = 0; ks < 8; ks++) {
        int ac = 8 * ks + t4;
        unsigned ah0 = sUH[ar0 + ac], ah1 = sUH[ar1 + ac];
        unsigned ah2 = sUH[ar0 + ac + 4], ah3 = sUH[ar1 + ac + 4];
        unsigned al0 = sUL[ar0 + ac], al1 = sUL[ar1 + ac];
        unsigned al2 = sUL[ar0 + ac + 4], al3 = sUL[ar1 + ac + 4];
        int br = (8 * ks + t4) * 136 + 64 * wn + gq;
#pragma unroll
        for (int j = 0; j < 8; j++) {
            float bf0 = sW1[br + 8 * j];
            float bf1 = sW1[br + 4 * 136 + 8 * j];
            unsigned bh0, bl0, bh1, bl1;
            split2(bf0, bh0, bl0);
            split2(bf1, bh1, bl1);
            mma8(c1[j], ah0, ah1, ah2, ah3, bh0, bh1);
            mma8(c1[j], ah0, ah1, ah2, ah3, bl0, bl1);
            mma8(c1[j], al0, al1, al2, al3, bh0, bh1);
        }
    }
    __syncthreads();   // done reading sU region

    // ---- epilogue 1: bias, store hid fp32 ----
    int r0 = 16 * wm + gq, r1 = r0 + 8;
#pragma unroll
    for (int j = 0; j < 8; j++) {
        int cb = 64 * wn + 8 * j + 2 * t4;
        float2 bb = *(const float2*)&b1g[cb];
        sHid[r0 * 132 + cb]     = c1[j][0] + bb.x;
        sHid[r0 * 132 + cb + 1] = c1[j][1] + bb.y;
        sHid[r1 * 132 + cb]     = c1[j][2] + bb.x;
        sHid[r1 * 132 + cb + 1] = c1[j][3] + bb.y;
    }
    __syncthreads();

    // ---- LayerNorm(128) + relu, warp per row ----
    {
        float gm0 = gamg[lane], gm1 = gamg[lane + 32];
        float gm2 = gamg[lane + 64], gm3 = gamg[lane + 96];
        float bt0 = betg[lane], bt1 = betg[lane + 32];
        float bt2 = betg[lane + 64], bt3 = betg[lane + 96];
        for (int r = w * 8; r < w * 8 + 8; r++) {
            float v0 = sHid[r * 132 + lane];
            float v1 = sHid[r * 132 + lane + 32];
            float v2 = sHid[r * 132 + lane + 64];
            float v3 = sHid[r * 132 + lane + 96];
            float s = v0 + v1 + v2 + v3;
            float sq = v0 * v0 + v1 * v1 + v2 * v2 + v3 * v3;
            for (int o = 16; o; o >>= 1) {
                s  += __shfl_xor_sync(0xffffffffu, s, o);
                sq += __shfl_xor_sync(0xffffffffu, sq, o);
            }
            float mu = s * (1.f / 128.f);
            float var = sq * (1.f / 128.f) - mu * mu;
            float rs = rsqrtf(var + 1e-5f);
            sHid[r * 132 + lane]      = fmaxf((v0 - mu) * rs * gm0 + bt0, 0.f);
            sHid[r * 132 + lane + 32] = fmaxf((v1 - mu) * rs * gm1 + bt1, 0.f);
            sHid[r * 132 + lane + 64] = fmaxf((v2 - mu) * rs * gm2 + bt2, 0.f);
            sHid[r * 132 + lane + 96] = fmaxf((v3 - mu) * rs * gm3 + bt3, 0.f);
        }
    }
    __syncthreads();

    // ---- GEMM2: out[64][64] = act[64][128] @ W2[128][64] ----
    float c2[4][4];
#pragma unroll
    for (int j = 0; j < 4; j++)
#pragma unroll
        for (int q = 0; q < 4; q++) c2[j][q] = 0.f;

    int hr0 = (16 * wm + gq) * 132, hr1 = hr0 + 8 * 132;
#pragma unroll
    for (int ks = 0; ks < 16; ks++) {
        int ac = 8 * ks + t4;
        float af0 = sHid[hr0 + ac], af1 = sHid[hr1 + ac];
        float af2 = sHid[hr0 + ac + 4], af3 = sHid[hr1 + ac + 4];
        unsigned ah0, al0, ah1, al1, ah2, al2, ah3, al3;
        split2(af0, ah0, al0); split2(af1, ah1, al1);
        split2(af2, ah2, al2); split2(af3, ah3, al3);
        int br = (8 * ks + t4) * 72 + 32 * wn + gq;
#pragma unroll
        for (int j = 0; j < 4; j++) {
            float bf0 = sW2[br + 8 * j];
            float bf1 = sW2[br + 4 * 72 + 8 * j];
            unsigned bh0, bl0, bh1, bl1;
            split2(bf0, bh0, bl0);
            split2(bf1, bh1, bl1);
            mma8(c2[j], ah0, ah1, ah2, ah3, bh0, bh1);
            mma8(c2[j], ah0, ah1, ah2, ah3, bl0, bl1);
            mma8(c2[j], al0, al1, al2, al3, bh0, bh1);
        }
    }

    // ---- epilogue 2: bias (+residual) -> g_h ----
    int node0 = n0 + r0, node1 = n0 + r1;
#pragma unroll
    for (int j = 0; j < 4; j++) {
        int cb = 32 * wn + 8 * j + 2 * t4;
        float2 bb = *(const float2*)&b2g[cb];
        if (node0 < NN) {
            float2 o = make_float2(c2[j][0] + bb.x, c2[j][1] + bb.y);
            float* dst = g_h + node0 * HH + cb;
            if (addm) { float2 p = *(const float2*)dst; o.x += p.x; o.y += p.y; }
            *(float2*)dst = o;
        }
        if (node1 < NN) {
            float2 o = make_float2(c2[j][2] + bb.x, c2[j][3] + bb.y);
            float* dst = g_h + node1 * HH + cb;
            if (addm) { float2 p = *(const float2*)dst; o.x += p.x; o.y += p.y; }
            *(float2*)dst = o;
        }
    }
}

// -------- final: relu(LN(h)) @ lin_W + lin_b ; also re-zero scratch --------
__global__ void k_final(const float* __restrict__ g, const float* __restrict__ b,
                        const float* __restrict__ lw, const float* __restrict__ lb,
                        float* __restrict__ out) {
    int gw = (blockIdx.x * blockDim.x + threadIdx.x) >> 5;
    if (gw >= NN) return;
    int lane = threadIdx.x & 31;
    if (lane == 1) g_wp[gw] = 0;
    if (gw < 128 && lane == 2) g_sflag[gw] = 0;

    float2 v = *(const float2*)(g_h + gw * HH + 2 * lane);
    float s = v.x + v.y, sq = v.x * v.x + v.y * v.y;
    for (int o = 16; o; o >>= 1) {
        s  += __shfl_xor_sync(0xffffffffu, s, o);
        sq += __shfl_xor_sync(0xffffffffu, sq, o);
    }
    float mu = s * 0.015625f;
    float var = sq * 0.015625f - mu * mu;
    float rs = rsqrtf(var + 1e-5f);
    float a0 = fmaxf((v.x - mu) * rs * g[2 * lane]     + b[2 * lane],     0.f);
    float a1 = fmaxf((v.y - mu) * rs * g[2 * lane + 1] + b[2 * lane + 1], 0.f);
    float o0 = a0 * lw[(2 * lane) * 3 + 0] + a1 * lw[(2 * lane + 1) * 3 + 0];
    float o1 = a0 * lw[(2 * lane) * 3 + 1] + a1 * lw[(2 * lane + 1) * 3 + 1];
    float o2 = a0 * lw[(2 * lane) * 3 + 2] + a1 * lw[(2 * lane + 1) * 3 + 2];
    for (int ww = 16; ww; ww >>= 1) {
        o0 += __shfl_xor_sync(0xffffffffu, o0, ww);
        o1 += __shfl_xor_sync(0xffffffffu, o1, ww);
        o2 += __shfl_xor_sync(0xffffffffu, o2, ww);
    }
    if (lane == 0) {
        out[gw * 3 + 0] = o0 + lb[0];
        out[gw * 3 + 1] = o1 + lb[1];
        out[gw * 3 + 2] = o2 + lb[2];
    }
}

// ---------------- launch ----------------
extern "C" void kernel_launch(void* const* d_in, const int* in_sizes, int n_in,
                              void* d_out, int out_size) {
    const float* x    = (const float*)d_in[0];
    const int*   ei   = (const int*)  d_in[1];
    const float* encW = (const float*)d_in[2];
    const float* encb = (const float*)d_in[3];
    const float* t    = (const float*)d_in[4];
    const float* W1   = (const float*)d_in[5];
    const float* b1   = (const float*)d_in[6];
    const float* mg   = (const float*)d_in[7];
    const float* mb   = (const float*)d_in[8];
    const float* W2   = (const float*)d_in[9];
    const float* b2   = (const float*)d_in[10];
    const float* lng  = (const float*)d_in[11];
    const float* lnb  = (const float*)d_in[12];
    const float* lw   = (const float*)d_in[13];
    const float* lb   = (const float*)d_in[14];
    float* out = (float*)d_out;

    const int SMEM_MLP = 26624 * 4;  // 106496 bytes
    cudaFuncSetAttribute(k_mlp, cudaFuncAttributeMaxDynamicSharedMemorySize, SMEM_MLP);

    const int WARP_BLOCKS = (NN * 32 + 255) / 256;
    const int MLP_BLOCKS  = (NN + 63) / 64;

    // CSR build
    k_enc_hist<<<(NN * HH + 255) / 256, 256>>>(x, encW, encb, ei);
    k_scan<<<NB_SCAN, 1024>>>();
    k_scatter<<<(NE + 255) / 256, 256>>>(ei);

    // layer 0 (launch index 3 = k_agg -> profiled slot)
    k_agg<<<WARP_BLOCKS, 256>>>(t + 0);
    k_mlp<<<MLP_BLOCKS, 256, SMEM_MLP>>>(W1, b1, mg, mb, W2, b2, 0);

    // layers 1, 2
    for (int i = 1; i < 3; i++) {
        k_lnrelu<<<WARP_BLOCKS, 256>>>(lng + i * HH, lnb + i * HH);
        k_agg<<<WARP_BLOCKS, 256>>>(t + i);
        k_mlp<<<MLP_BLOCKS, 256, SMEM_MLP>>>(W1 + i * HH * H2, b1 + i * H2,
                                             mg + i * H2, mb + i * H2,
                                             W2 + i * H2 * HH, b2 + i * HH, 1);
    }

    // final projection (+ scratch re-zero for next replay)
    k_final<<<WARP_BLOCKS, 256>>>(lng, lnb, lw, lb, out);
}

// round 5
// speedup vs baseline: 1.3601x; 1.0651x over previous
#include <cuda_runtime.h>
#include <cuda_bf16.h>

#define NN 100000
#define NE 1200000
#define HH 64
#define H2 128
#define NB_SCAN 98

// ---------------- device scratch (no allocations allowed) ----------------
__device__ float g_z[NN * HH];   // layer input features (fp32)
__device__ float g_h[NN * HH];   // residual stream (fp32)
__device__ unsigned g_uh[NN * 32];  // MLP input, bf16x2 hi words (k-pairs)
__device__ unsigned g_ul[NN * 32];  // MLP input, bf16x2 lo words
__device__ int   g_rowptr[NN + 1];
__device__ int   g_wp[NN];       // zeroed by previous replay's k_final
__device__ int   g_srcs[NE];
__device__ int   g_sval[128];
__device__ int   g_sincl[128];
__device__ int   g_sflag[128];   // tail-zeroed by k_final
// pre-split weights: [layer][k/2][n] packed bf16x2 (hi & lo parts)
__device__ unsigned g_w1h[3 * 4096], g_w1l[3 * 4096];
__device__ unsigned g_w2h[3 * 4096], g_w2l[3 * 4096];

// ---------------- helpers ----------------
__device__ __forceinline__ float ex2(float x) {
    float r; asm("ex2.approx.f32 %0, %1;" : "=f"(r) : "f"(x)); return r;
}
// pack {lo16 = bf16(xe), hi16 = bf16(xo)}  (xe = even k, xo = odd k)
__device__ __forceinline__ unsigned pk_bf2(float xe, float xo) {
    unsigned d;
    asm("cvt.rn.bf16x2.f32 %0, %1, %2;" : "=r"(d) : "f"(xo), "f"(xe));
    return d;
}
__device__ __forceinline__ float lo16f(unsigned w) { return __uint_as_float(w << 16); }
__device__ __forceinline__ float hi16f(unsigned w) { return __uint_as_float(w & 0xffff0000u); }
// split pair (xe,xo) into hi word + lo word
__device__ __forceinline__ void split_pair(float xe, float xo, unsigned& hw, unsigned& lw) {
    hw = pk_bf2(xe, xo);
    lw = pk_bf2(xe - lo16f(hw), xo - hi16f(hw));
}
__device__ __forceinline__ void mma16(float* c, unsigned a0, unsigned a1,
                                      unsigned a2, unsigned a3,
                                      unsigned b0, unsigned b1) {
    asm("mma.sync.aligned.m16n8k16.row.col.f32.bf16.bf16.f32 "
        "{%0,%1,%2,%3}, {%4,%5,%6,%7}, {%8,%9}, {%0,%1,%2,%3};"
        : "+f"(c[0]), "+f"(c[1]), "+f"(c[2]), "+f"(c[3])
        : "r"(a0), "r"(a1), "r"(a2), "r"(a3), "r"(b0), "r"(b1));
}

// ------ launch 0: encoder + degree histogram + weight pre-split ------
__global__ void k_enc_hist(const float* __restrict__ x, const float* __restrict__ W,
                           const float* __restrict__ b, const int* __restrict__ ei,
                           const float* __restrict__ W1g, const float* __restrict__ W2g) {
    int idx = blockIdx.x * blockDim.x + threadIdx.x;
    if (idx == 0) g_rowptr[NN] = NE;
    if (idx < NE) atomicAdd(&g_wp[ei[NE + idx]], 1);
    if (idx < NN * HH) {
        int n = idx >> 6, c = idx & 63;
        g_z[idx] = x[n * 3] * W[c] + x[n * 3 + 1] * W[HH + c]
                 + x[n * 3 + 2] * W[2 * HH + c] + b[c];
    }
    if (idx < 3 * 4096) {   // W1 split: [l][kp][n], kp in 0..31, n in 0..127
        int l = idx >> 12, r = idx & 4095, kp = r >> 7, n = r & 127;
        const float* Wl = W1g + l * (HH * H2);
        unsigned hw, lw;
        split_pair(Wl[(2 * kp) * H2 + n], Wl[(2 * kp + 1) * H2 + n], hw, lw);
        g_w1h[idx] = hw; g_w1l[idx] = lw;
    }
    if (idx < 3 * 4096) {   // W2 split: [l][kp][n], kp in 0..63, n in 0..63
        int l = idx >> 12, r = idx & 4095, kp = r >> 6, n = r & 63;
        const float* Wl = W2g + l * (H2 * HH);
        unsigned hw, lw;
        split_pair(Wl[(2 * kp) * HH + n], Wl[(2 * kp + 1) * HH + n], hw, lw);
        g_w2h[idx] = hw; g_w2l[idx] = lw;
    }
}

// ------------- launch 1: single-pass scan (decoupled lookback) -------------
__global__ void k_scan() {
    __shared__ int wsum[32];
    __shared__ int s_excl;
    int t = threadIdx.x, b = blockIdx.x;
    int lane = t & 31, wid = t >> 5;
    int i = b * 1024 + t;
    int x = (i < NN) ? g_wp[i] : 0;

    int v = x;
#pragma unroll
    for (int d = 1; d < 32; d <<= 1) {
        int u = __shfl_up_sync(0xffffffffu, v, d);
        if (lane >= d) v += u;
    }
    if (lane == 31) wsum[wid] = v;
    __syncthreads();
    if (wid == 0) {
        int w = wsum[lane];
#pragma unroll
        for (int d = 1; d < 32; d <<= 1) {
            int u = __shfl_up_sync(0xffffffffu, w, d);
            if (lane >= d) w += u;
        }
        wsum[lane] = w;
    }
    __syncthreads();
    int incl = v + (wid ? wsum[wid - 1] : 0);
    int bsum = wsum[31];

    if (t == 0) {
        if (b == 0) {
            g_sincl[0] = bsum; __threadfence(); g_sflag[0] = 2;
            s_excl = 0;
        } else {
            g_sval[b] = bsum; __threadfence(); g_sflag[b] = 1;
            int excl = 0, j = b - 1;
            while (true) {
                int f;
                do { f = ((volatile int*)g_sflag)[j]; } while (f == 0);
                __threadfence();
                if (f == 2) { excl += ((volatile int*)g_sincl)[j]; break; }
                excl += ((volatile int*)g_sval)[j]; j--;
            }
            g_sincl[b] = excl + bsum; __threadfence(); g_sflag[b] = 2;
            s_excl = excl;
        }
    }
    __syncthreads();
    if (i < NN) {
        int e = s_excl + incl - x;
        g_rowptr[i] = e;
        g_wp[i] = e;
    }
}

// ------------- launch 2: scatter src ids into CSR -------------
__global__ void k_scatter(const int* __restrict__ ei) {
    int e = blockIdx.x * blockDim.x + threadIdx.x;
    if (e < NE) {
        int d = ei[NE + e];
        int p = atomicAdd(&g_wp[d], 1);
        g_srcs[p] = ei[e];
    }
}

// ------- single-pass softmax aggregation (warp/node); emits bf16 splits ---
__global__ void k_agg(const float* __restrict__ tptr) {
    int gw = (blockIdx.x * blockDim.x + threadIdx.x) >> 5;
    if (gw >= NN) return;
    int lane = threadIdx.x & 31;
    int beg = g_rowptr[gw], end = g_rowptr[gw + 1];
    float tt = __ldg(tptr);
    float tl2 = tt * 1.44269504f;     // t * log2(e)
    float eoff = 1e-7f * tl2;

    float z0 = 0.f, z1 = 0.f, s0 = 0.f, s1 = 0.f;
    for (int base = beg; base < end; base += 32) {
        int nn = end - base; if (nn > 32) nn = 32;
        int sid = (base + lane < end) ? __ldg(&g_srcs[base + lane]) : 0;
#pragma unroll 4
        for (int j = 0; j < nn; j++) {
            int s = __shfl_sync(0xffffffffu, sid, j);
            float2 v = *(const float2*)(g_z + s * HH + 2 * lane);
            float r0 = fmaxf(v.x, 0.f), r1 = fmaxf(v.y, 0.f);
            float w0 = ex2(fmaf(r0, tl2, eoff));
            float w1 = ex2(fmaf(r1, tl2, eoff));
            z0 += w0; z1 += w1;
            s0 = fmaf(r0 + 1e-7f, w0, s0);
            s1 = fmaf(r1 + 1e-7f, w1, s1);
        }
    }
    float2 zz = *(const float2*)(g_z + gw * HH + 2 * lane);
    float ox = zz.x, oy = zz.y;
    if (end > beg) {
        ox += __fdividef(s0, z0);
        oy += __fdividef(s1, z1);
    }
    unsigned hw, lw;
    split_pair(ox, oy, hw, lw);        // ch (2*lane, 2*lane+1) -> k-pair word
    g_uh[gw * 32 + lane] = hw;
    g_ul[gw * 32 + lane] = lw;
}

// ---------------- outer pre-conv z = relu(LN(h)) ----------------
__global__ void k_lnrelu(const float* __restrict__ g, const float* __restrict__ b) {
    int gw = (blockIdx.x * blockDim.x + threadIdx.x) >> 5;
    if (gw >= NN) return;
    int lane = threadIdx.x & 31;
    float2 v = *(const float2*)(g_h + gw * HH + 2 * lane);
    float s = v.x + v.y, sq = v.x * v.x + v.y * v.y;
    for (int o = 16; o; o >>= 1) {
        s  += __shfl_xor_sync(0xffffffffu, s, o);
        sq += __shfl_xor_sync(0xffffffffu, sq, o);
    }
    float mu = s * 0.015625f;
    float var = sq * 0.015625f - mu * mu;
    float rs = rsqrtf(var + 1e-5f);
    float2 o2;
    o2.x = fmaxf((v.x - mu) * rs * g[2 * lane]     + b[2 * lane],     0.f);
    o2.y = fmaxf((v.y - mu) * rs * g[2 * lane + 1] + b[2 * lane + 1], 0.f);
    *(float2*)(g_z + gw * HH + 2 * lane) = o2;
}

// -------- fused MLP on bf16 tensor cores (3-term emulated fp32) ----------
// block = 64 nodes, 256 threads (8 warps).
// smem (u32 words, total 26368 = 105472 B):
//   [0, 8704)      region1: sUH[64][36] + sUL[64][36]  -> later sHH[64][68]+sHL[64][68]
//   [8704, 17920)  region2: sW1H[32][136]+sW1L         -> later sW2H[64][72]+sW2L
//   [17920, 26368) region3: sHid fp32 [64][132]
extern __shared__ unsigned smu[];
__global__ __launch_bounds__(256, 2) void k_mlp(
    const float* __restrict__ b1g, const float* __restrict__ gamg,
    const float* __restrict__ betg, const float* __restrict__ b2g,
    int layer, int addm)
{
    unsigned* sUH  = smu;            // [64][36]
    unsigned* sUL  = smu + 2304;     // [64][36]
    unsigned* sHH  = smu;            // [64][68]
    unsigned* sHL  = smu + 4352;     // [64][68]
    unsigned* sW1H = smu + 8704;     // [32][136]
    unsigned* sW1L = smu + 13056;    // [32][136]
    unsigned* sW2H = smu + 8704;     // [64][72]
    unsigned* sW2L = smu + 13312;    // [64][72]
    float*    sHid = (float*)(smu + 17920);  // [64][132]

    int tid = threadIdx.x;
    int n0 = blockIdx.x * 64;
    int w = tid >> 5, lane = tid & 31;
    int g = lane >> 2, t4 = lane & 3;
    int wm = w & 3, wn = w >> 2;
    int lofs = layer * 4096;

    // ---- load U splits (packed) ----
    for (int i = tid; i < 2048; i += 256) {
        int r = i >> 5, c = i & 31;
        int node = n0 + r;
        unsigned h = 0, lo = 0;
        if (node < NN) { h = g_uh[node * 32 + c]; lo = g_ul[node * 32 + c]; }
        sUH[r * 36 + c] = h;
        sUL[r * 36 + c] = lo;
    }
    // ---- load W1 splits ----
    for (int i = tid; i < 4096; i += 256) {
        int kp = i >> 7, n = i & 127;
        sW1H[kp * 136 + n] = g_w1h[lofs + i];
        sW1L[kp * 136 + n] = g_w1l[lofs + i];
    }
    __syncthreads();

    // ---- GEMM1: hid[64][128] = U[64][64] @ W1[64][128], 3-term bf16 ----
    float c1[8][4];
#pragma unroll
    for (int j = 0; j < 8; j++)
#pragma unroll
        for (int q = 0; q < 4; q++) c1[j][q] = 0.f;

    int ar0 = (16 * wm + g) * 36, ar1 = ar0 + 8 * 36;
#pragma unroll
    for (int ks = 0; ks < 4; ks++) {
        int ac = 8 * ks + t4;
        unsigned ah0 = sUH[ar0 + ac],     ah1 = sUH[ar1 + ac];
        unsigned ah2 = sUH[ar0 + ac + 4], ah3 = sUH[ar1 + ac + 4];
        unsigned al0 = sUL[ar0 + ac],     al1 = sUL[ar1 + ac];
        unsigned al2 = sUL[ar0 + ac + 4], al3 = sUL[ar1 + ac + 4];
        int br0 = (8 * ks + t4) * 136, br1 = (8 * ks + t4 + 4) * 136;
#pragma unroll
        for (int j = 0; j < 8; j++) {
            int n = 64 * wn + 8 * j + g;
            unsigned bh0 = sW1H[br0 + n], bh1 = sW1H[br1 + n];
            unsigned bl0 = sW1L[br0 + n], bl1 = sW1L[br1 + n];
            mma16(c1[j], ah0, ah1, ah2, ah3, bh0, bh1);
            mma16(c1[j], ah0, ah1, ah2, ah3, bl0, bl1);
            mma16(c1[j], al0, al1, al2, al3, bh0, bh1);
        }
    }

    // ---- epilogue 1: bias -> sHid fp32 (region3, no overlap) ----
    int r0 = 16 * wm + g, r1 = r0 + 8;
#pragma unroll
    for (int j = 0; j < 8; j++) {
        int cb = 64 * wn + 8 * j + 2 * t4;
        float2 bb = *(const float2*)&b1g[cb];
        *(float2*)&sHid[r0 * 132 + cb] = make_float2(c1[j][0] + bb.x, c1[j][1] + bb.y);
        *(float2*)&sHid[r1 * 132 + cb] = make_float2(c1[j][2] + bb.x, c1[j][3] + bb.y);
    }
    __syncthreads();

    // ---- load W2 splits (overwrites W1 region) ----
    for (int i = tid; i < 4096; i += 256) {
        int kp = i >> 6, n = i & 63;
        sW2H[kp * 72 + n] = g_w2h[lofs + i];
        sW2L[kp * 72 + n] = g_w2l[lofs + i];
    }

    // ---- LayerNorm(128) + relu; write pre-split bf16 (overwrites sU) ----
    {
        float2 ga = *(const float2*)&gamg[2 * lane];
        float2 gb = *(const float2*)&gamg[64 + 2 * lane];
        float2 ba = *(const float2*)&betg[2 * lane];
        float2 bbv = *(const float2*)&betg[64 + 2 * lane];
        for (int r = w * 8; r < w * 8 + 8; r++) {
            float2 va = *(const float2*)&sHid[r * 132 + 2 * lane];
            float2 vb = *(const float2*)&sHid[r * 132 + 64 + 2 * lane];
            float s = va.x + va.y + vb.x + vb.y;
            float sq = va.x * va.x + va.y * va.y + vb.x * vb.x + vb.y * vb.y;
            for (int o = 16; o; o >>= 1) {
                s  += __shfl_xor_sync(0xffffffffu, s, o);
                sq += __shfl_xor_sync(0xffffffffu, sq, o);
            }
            float mu = s * (1.f / 128.f);
            float var = sq * (1.f / 128.f) - mu * mu;
            float rs = rsqrtf(var + 1e-5f);
            float h0 = fmaxf((va.x - mu) * rs * ga.x + ba.x, 0.f);
            float h1 = fmaxf((va.y - mu) * rs * ga.y + ba.y, 0.f);
            float h2 = fmaxf((vb.x - mu) * rs * gb.x + bbv.x, 0.f);
            float h3 = fmaxf((vb.y - mu) * rs * gb.y + bbv.y, 0.f);
            unsigned hw0, lw0, hw1, lw1;
            split_pair(h0, h1, hw0, lw0);
            split_pair(h2, h3, hw1, lw1);
            sHH[r * 68 + lane] = hw0; sHH[r * 68 + 32 + lane] = hw1;
            sHL[r * 68 + lane] = lw0; sHL[r * 68 + 32 + lane] = lw1;
        }
    }
    __syncthreads();

    // ---- GEMM2: out[64][64] = act[64][128] @ W2[128][64] ----
    float c2[4][4];
#pragma unroll
    for (int j = 0; j < 4; j++)
#pragma unroll
        for (int q = 0; q < 4; q++) c2[j][q] = 0.f;

    int hr0 = (16 * wm + g) * 68, hr1 = hr0 + 8 * 68;
#pragma unroll
    for (int ks = 0; ks < 8; ks++) {
        int ac = 8 * ks + t4;
        unsigned ah0 = sHH[hr0 + ac],     ah1 = sHH[hr1 + ac];
        unsigned ah2 = sHH[hr0 + ac + 4], ah3 = sHH[hr1 + ac + 4];
        unsigned al0 = sHL[hr0 + ac],     al1 = sHL[hr1 + ac];
        unsigned al2 = sHL[hr0 + ac + 4], al3 = sHL[hr1 + ac + 4];
        int br0 = (8 * ks + t4) * 72, br1 = (8 * ks + t4 + 4) * 72;
#pragma unroll
        for (int j = 0; j < 4; j++) {
            int n = 32 * wn + 8 * j + g;
            unsigned bh0 = sW2H[br0 + n], bh1 = sW2H[br1 + n];
            unsigned bl0 = sW2L[br0 + n], bl1 = sW2L[br1 + n];
            mma16(c2[j], ah0, ah1, ah2, ah3, bh0, bh1);
            mma16(c2[j], ah0, ah1, ah2, ah3, bl0, bl1);
            mma16(c2[j], al0, al1, al2, al3, bh0, bh1);
        }
    }

    // ---- epilogue 2: bias (+residual) -> g_h ----
    int node0 = n0 + r0, node1 = n0 + r1;
#pragma unroll
    for (int j = 0; j < 4; j++) {
        int cb = 32 * wn + 8 * j + 2 * t4;
        float2 bb = *(const float2*)&b2g[cb];
        if (node0 < NN) {
            float2 o = make_float2(c2[j][0] + bb.x, c2[j][1] + bb.y);
            float* dst = g_h + node0 * HH + cb;
            if (addm) { float2 p = *(const float2*)dst; o.x += p.x; o.y += p.y; }
            *(float2*)dst = o;
        }
        if (node1 < NN) {
            float2 o = make_float2(c2[j][2] + bb.x, c2[j][3] + bb.y);
            float* dst = g_h + node1 * HH + cb;
            if (addm) { float2 p = *(const float2*)dst; o.x += p.x; o.y += p.y; }
            *(float2*)dst = o;
        }
    }
}

// -------- final: relu(LN(h)) @ lin_W + lin_b ; also re-zero scratch --------
__global__ void k_final(const float* __restrict__ g, const float* __restrict__ b,
                        const float* __restrict__ lw, const float* __restrict__ lb,
                        float* __restrict__ out) {
    int gw = (blockIdx.x * blockDim.x + threadIdx.x) >> 5;
    if (gw >= NN) return;
    int lane = threadIdx.x & 31;
    if (lane == 1) g_wp[gw] = 0;
    if (gw < 128 && lane == 2) g_sflag[gw] = 0;

    float2 v = *(const float2*)(g_h + gw * HH + 2 * lane);
    float s = v.x + v.y, sq = v.x * v.x + v.y * v.y;
    for (int o = 16; o; o >>= 1) {
        s  += __shfl_xor_sync(0xffffffffu, s, o);
        sq += __shfl_xor_sync(0xffffffffu, sq, o);
    }
    float mu = s * 0.015625f;
    float var = sq * 0.015625f - mu * mu;
    float rs = rsqrtf(var + 1e-5f);
    float a0 = fmaxf((v.x - mu) * rs * g[2 * lane]     + b[2 * lane],     0.f);
    float a1 = fmaxf((v.y - mu) * rs * g[2 * lane + 1] + b[2 * lane + 1], 0.f);
    float o0 = a0 * lw[(2 * lane) * 3 + 0] + a1 * lw[(2 * lane + 1) * 3 + 0];
    float o1 = a0 * lw[(2 * lane) * 3 + 1] + a1 * lw[(2 * lane + 1) * 3 + 1];
    float o2 = a0 * lw[(2 * lane) * 3 + 2] + a1 * lw[(2 * lane + 1) * 3 + 2];
    for (int ww = 16; ww; ww >>= 1) {
        o0 += __shfl_xor_sync(0xffffffffu, o0, ww);
        o1 += __shfl_xor_sync(0xffffffffu, o1, ww);
        o2 += __shfl_xor_sync(0xffffffffu, o2, ww);
    }
    if (lane == 0) {
        out[gw * 3 + 0] = o0 + lb[0];
        out[gw * 3 + 1] = o1 + lb[1];
        out[gw * 3 + 2] = o2 + lb[2];
    }
}

// ---------------- launch ----------------
extern "C" void kernel_launch(void* const* d_in, const int* in_sizes, int n_in,
                              void* d_out, int out_size) {
    const float* x    = (const float*)d_in[0];
    const int*   ei   = (const int*)  d_in[1];
    const float* encW = (const float*)d_in[2];
    const float* encb = (const float*)d_in[3];
    const float* t    = (const float*)d_in[4];
    const float* W1   = (const float*)d_in[5];
    const float* b1   = (const float*)d_in[6];
    const float* mg   = (const float*)d_in[7];
    const float* mb   = (const float*)d_in[8];
    const float* W2   = (const float*)d_in[9];
    const float* b2   = (const float*)d_in[10];
    const float* lng  = (const float*)d_in[11];
    const float* lnb  = (const float*)d_in[12];
    const float* lw   = (const float*)d_in[13];
    const float* lb   = (const float*)d_in[14];
    float* out = (float*)d_out;

    const int SMEM_MLP = 26368 * 4;  // 105472 bytes
    cudaFuncSetAttribute(k_mlp, cudaFuncAttributeMaxDynamicSharedMemorySize, SMEM_MLP);

    const int WARP_BLOCKS = (NN * 32 + 255) / 256;
    const int MLP_BLOCKS  = (NN + 63) / 64;

    // CSR build + encoder + weight pre-split (launches 0..2)
    k_enc_hist<<<(NN * HH + 255) / 256, 256>>>(x, encW, encb, ei, W1, W2);
    k_scan<<<NB_SCAN, 1024>>>();
    k_scatter<<<(NE + 255) / 256, 256>>>(ei);

    // layer 0 (launch index 3 = k_agg -> profiled slot)
    k_agg<<<WARP_BLOCKS, 256>>>(t + 0);
    k_mlp<<<MLP_BLOCKS, 256, SMEM_MLP>>>(b1, mg, mb, b2, 0, 0);

    // layers 1, 2
    for (int i = 1; i < 3; i++) {
        k_lnrelu<<<WARP_BLOCKS, 256>>>(lng + i * HH, lnb + i * HH);
        k_agg<<<WARP_BLOCKS, 256>>>(t + i);
        k_mlp<<<MLP_BLOCKS, 256, SMEM_MLP>>>(b1 + i * H2, mg + i * H2, mb + i * H2,
                                             b2 + i * HH, i, 1);
    }

    // final projection (+ scratch re-zero for next replay)
    k_final<<<WARP_BLOCKS, 256>>>(lng, lnb, lw, lb, out);
}

// round 7
// speedup vs baseline: 1.8360x; 1.3499x over previous
#include <cuda_runtime.h>
#include <cuda_bf16.h>
#include <cstdint>

#define NN 100000
#define NE 1200000
#define HH 64
#define H2 128
#define NB_SCAN 98

// ---------------- device scratch (no allocations allowed) ----------------
__device__ float g_z[NN * HH];      // layer input features (fp32)
__device__ float g_h[NN * HH];      // residual stream (fp32)
__device__ unsigned g_uh[NN * 32];  // MLP input, bf16x2 hi words (k-pairs)
__device__ unsigned g_ul[NN * 32];  // MLP input, bf16x2 lo words
__device__ int   g_rowptr[NN + 1];
__device__ int   g_wp[NN];          // zeroed by previous replay's k_final
__device__ int   g_srcs[NE];
__device__ int   g_sval[128];
__device__ int   g_sincl[128];
__device__ int   g_sflag[128];      // tail-zeroed by k_final
// pre-split weights, [n][kp] rows (k contiguous as bf16):
//   W1: idx = l*4096 + n*32 + kp   (n 0..127, kp 0..31)
//   W2: idx = l*4096 + n*64 + kp   (n 0..63,  kp 0..63)
__device__ unsigned g_w1h[3 * 4096], g_w1l[3 * 4096];
__device__ unsigned g_w2h[3 * 4096], g_w2l[3 * 4096];

// ---------------- helpers ----------------
__device__ __forceinline__ float ex2(float x) {
    float r; asm("ex2.approx.f32 %0, %1;" : "=f"(r) : "f"(x)); return r;
}
__device__ __forceinline__ unsigned pk_bf2(float xe, float xo) {
    unsigned d;
    asm("cvt.rn.bf16x2.f32 %0, %1, %2;" : "=r"(d) : "f"(xo), "f"(xe));
    return d;  // lo16 = bf16(xe), hi16 = bf16(xo)
}
__device__ __forceinline__ float lo16f(unsigned w) { return __uint_as_float(w << 16); }
__device__ __forceinline__ float hi16f(unsigned w) { return __uint_as_float(w & 0xffff0000u); }
__device__ __forceinline__ void split_pair(float xe, float xo, unsigned& hw, unsigned& lw) {
    hw = pk_bf2(xe, xo);
    lw = pk_bf2(xe - lo16f(hw), xo - hi16f(hw));
}
__device__ __forceinline__ uint32_t smem_u32(const void* p) {
    uint32_t a;
    asm("{ .reg .u64 t; cvta.to.shared.u64 t, %1; cvt.u32.u64 %0, t; }" : "=r"(a) : "l"(p));
    return a;
}
__device__ __forceinline__ void mma16(float* c, unsigned a0, unsigned a1,
                                      unsigned a2, unsigned a3,
                                      unsigned b0, unsigned b1) {
    asm("mma.sync.aligned.m16n8k16.row.col.f32.bf16.bf16.f32 "
        "{%0,%1,%2,%3}, {%4,%5,%6,%7}, {%8,%9}, {%0,%1,%2,%3};"
        : "+f"(c[0]), "+f"(c[1]), "+f"(c[2]), "+f"(c[3])
        : "r"(a0), "r"(a1), "r"(a2), "r"(a3), "r"(b0), "r"(b1));
}
__device__ __forceinline__ void ldsm4(unsigned& r0, unsigned& r1, unsigned& r2,
                                      unsigned& r3, uint32_t addr) {
    asm volatile("ldmatrix.sync.aligned.m8n8.x4.shared.b16 {%0,%1,%2,%3}, [%4];"
                 : "=r"(r0), "=r"(r1), "=r"(r2), "=r"(r3) : "r"(addr));
}

// ------ launch 0: encoder + degree histogram + weight pre-split ------
__global__ void k_enc_hist(const float* __restrict__ x, const float* __restrict__ W,
                           const float* __restrict__ b, const int* __restrict__ ei,
                           const float* __restrict__ W1g, const float* __restrict__ W2g) {
    int idx = blockIdx.x * blockDim.x + threadIdx.x;
    if (idx == 0) g_rowptr[NN] = NE;
    if (idx < NE) atomicAdd(&g_wp[ei[NE + idx]], 1);
    if (idx < NN * HH) {
        int n = idx >> 6, c = idx & 63;
        g_z[idx] = x[n * 3] * W[c] + x[n * 3 + 1] * W[HH + c]
                 + x[n * 3 + 2] * W[2 * HH + c] + b[c];
    }
    if (idx < 3 * 4096) {   // W1^T: idx = l*4096 + n*32 + kp
        int l = idx >> 12, r = idx & 4095, n = r >> 5, kp = r & 31;
        const float* Wl = W1g + l * (HH * H2);
        unsigned hw, lw;
        split_pair(Wl[(2 * kp) * H2 + n], Wl[(2 * kp + 1) * H2 + n], hw, lw);
        g_w1h[idx] = hw; g_w1l[idx] = lw;
    }
    if (idx < 3 * 4096) {   // W2^T: idx = l*4096 + n*64 + kp
        int l = idx >> 12, r = idx & 4095, n = r >> 6, kp = r & 63;
        const float* Wl = W2g + l * (H2 * HH);
        unsigned hw, lw;
        split_pair(Wl[(2 * kp) * HH + n], Wl[(2 * kp + 1) * HH + n], hw, lw);
        g_w2h[idx] = hw; g_w2l[idx] = lw;
    }
}

// ------------- launch 1: single-pass scan (decoupled lookback) -------------
__global__ void k_scan() {
    __shared__ int wsum[32];
    __shared__ int s_excl;
    int t = threadIdx.x, b = blockIdx.x;
    int lane = t & 31, wid = t >> 5;
    int i = b * 1024 + t;
    int x = (i < NN) ? g_wp[i] : 0;

    int v = x;
#pragma unroll
    for (int d = 1; d < 32; d <<= 1) {
        int u = __shfl_up_sync(0xffffffffu, v, d);
        if (lane >= d) v += u;
    }
    if (lane == 31) wsum[wid] = v;
    __syncthreads();
    if (wid == 0) {
        int w = wsum[lane];
#pragma unroll
        for (int d = 1; d < 32; d <<= 1) {
            int u = __shfl_up_sync(0xffffffffu, w, d);
            if (lane >= d) w += u;
        }
        wsum[lane] = w;
    }
    __syncthreads();
    int incl = v + (wid ? wsum[wid - 1] : 0);
    int bsum = wsum[31];

    if (t == 0) {
        if (b == 0) {
            g_sincl[0] = bsum; __threadfence(); g_sflag[0] = 2;
            s_excl = 0;
        } else {
            g_sval[b] = bsum; __threadfence(); g_sflag[b] = 1;
            int excl = 0, j = b - 1;
            while (true) {
                int f;
                do { f = ((volatile int*)g_sflag)[j]; } while (f == 0);
                __threadfence();
                if (f == 2) { excl += ((volatile int*)g_sincl)[j]; break; }
                excl += ((volatile int*)g_sval)[j]; j--;
            }
            g_sincl[b] = excl + bsum; __threadfence(); g_sflag[b] = 2;
            s_excl = excl;
        }
    }
    __syncthreads();
    if (i < NN) {
        int e = s_excl + incl - x;
        g_rowptr[i] = e;
        g_wp[i] = e;
    }
}

// ------------- launch 2: scatter src ids into CSR -------------
__global__ void k_scatter(const int* __restrict__ ei) {
    int e = blockIdx.x * blockDim.x + threadIdx.x;
    if (e < NE) {
        int d = ei[NE + e];
        int p = atomicAdd(&g_wp[d], 1);
        g_srcs[p] = ei[e];
    }
}

// ------- single-pass softmax aggregation (warp/node); emits bf16 splits ---
// eps folds out: softmax shift-invariant in logits; message sum gets +eps.
__global__ void k_agg(const float* __restrict__ tptr) {
    int gw = (blockIdx.x * blockDim.x + threadIdx.x) >> 5;
    if (gw >= NN) return;
    int lane = threadIdx.x & 31;
    int beg = g_rowptr[gw], end = g_rowptr[gw + 1];
    float tl2 = __ldg(tptr) * 1.44269504f;

    float z0 = 0.f, z1 = 0.f, s0 = 0.f, s1 = 0.f;
    for (int base = beg; base < end; base += 32) {
        int nn = end - base; if (nn > 32) nn = 32;
        int sid = (base + lane < end) ? __ldg(&g_srcs[base + lane]) : 0;
#pragma unroll 4
        for (int j = 0; j < nn; j++) {
            int s = __shfl_sync(0xffffffffu, sid, j);
            float2 v = *(const float2*)(g_z + s * HH + 2 * lane);
            float r0 = fmaxf(v.x, 0.f), r1 = fmaxf(v.y, 0.f);
            float w0 = ex2(r0 * tl2);
            float w1 = ex2(r1 * tl2);
            z0 += w0; z1 += w1;
            s0 = fmaf(r0, w0, s0);
            s1 = fmaf(r1, w1, s1);
        }
    }
    float2 zz = *(const float2*)(g_z + gw * HH + 2 * lane);
    float ox = zz.x, oy = zz.y;
    if (end > beg) {
        ox += __fdividef(s0, z0) + 1e-7f;
        oy += __fdividef(s1, z1) + 1e-7f;
    }
    unsigned hw, lw;
    split_pair(ox, oy, hw, lw);
    g_uh[gw * 32 + lane] = hw;
    g_ul[gw * 32 + lane] = lw;
}

// ---------------- outer pre-conv z = relu(LN(h)) ----------------
__global__ void k_lnrelu(const float* __restrict__ g, const float* __restrict__ b) {
    int gw = (blockIdx.x * blockDim.x + threadIdx.x) >> 5;
    if (gw >= NN) return;
    int lane = threadIdx.x & 31;
    float2 v = *(const float2*)(g_h + gw * HH + 2 * lane);
    float s = v.x + v.y, sq = v.x * v.x + v.y * v.y;
    for (int o = 16; o; o >>= 1) {
        s  += __shfl_xor_sync(0xffffffffu, s, o);
        sq += __shfl_xor_sync(0xffffffffu, sq, o);
    }
    float mu = s * 0.015625f;
    float var = sq * 0.015625f - mu * mu;
    float rs = rsqrtf(var + 1e-5f);
    float2 o2;
    o2.x = fmaxf((v.x - mu) * rs * g[2 * lane]     + b[2 * lane],     0.f);
    o2.y = fmaxf((v.y - mu) * rs * g[2 * lane + 1] + b[2 * lane + 1], 0.f);
    *(float2*)(g_z + gw * HH + 2 * lane) = o2;
}

// -------- fused MLP: bf16 mma.sync + ldmatrix, 3-term emulated fp32 -------
// block = 64 nodes, 256 threads (8 warps: wm = w&3 row-tile, wn = w>>2 col-half)
// smem word map (27328 words = 109312 B):
//   0    psum[128] | 128 psq[128]
//   256  b1[128] | 384 gam[128] | 512 bet[128] | 640 b2[64]
//   704  region A: sUH[64][36], sUL @+2304  -> later sHH[64][68], sHL @+4352
//   9408 sW1H[128][36] | 14016 sW1L
//   18624 sW2H[64][68] | 22976 sW2L   (end 27328)
#define W_PSUM 0
#define W_PSQ  128
#define W_B1   256
#define W_GAM  384
#define W_BET  512
#define W_B2   640
#define W_A    704
#define W_UH   (W_A)
#define W_UL   (W_A + 2304)
#define W_HH   (W_A)
#define W_HL   (W_A + 4352)
#define W_W1H  9408
#define W_W1L  14016
#define W_W2H  18624
#define W_W2L  22976
#define SMEM_MLP_BYTES (27328 * 4)

extern __shared__ unsigned smw[];
__global__ __launch_bounds__(256, 2) void k_mlp(
    const float* __restrict__ b1g, const float* __restrict__ gamg,
    const float* __restrict__ betg, const float* __restrict__ b2g,
    int layer, int addm)
{
    float* smf = (float*)smw;
    int tid = threadIdx.x, w = tid >> 5, lane = tid & 31;
    int g = lane >> 2, t4 = lane & 3;
    int wm = w & 3, wn = w >> 2;
    int n0 = blockIdx.x * 64;
    int lofs = layer * 4096;

    // params
    if (tid < 128) {
        smf[W_B1 + tid]  = b1g[tid];
        smf[W_GAM + tid] = gamg[tid];
        smf[W_BET + tid] = betg[tid];
        if (tid < 64) smf[W_B2 + tid] = b2g[tid];
    }
    // U tiles [64][36] (kp contiguous)
    for (int i = tid * 4; i < 2048; i += 1024) {
        int r = i >> 5, c = i & 31;
        int node = n0 + r;
        uint4 hv = make_uint4(0, 0, 0, 0), lv = hv;
        if (node < NN) {
            hv = *(const uint4*)&g_uh[node * 32 + c];
            lv = *(const uint4*)&g_ul[node * 32 + c];
        }
        *(uint4*)&smw[W_UH + r * 36 + c] = hv;
        *(uint4*)&smw[W_UL + r * 36 + c] = lv;
    }
    // W1 [128][36]
    for (int i = tid * 4; i < 4096; i += 1024) {
        int r = i >> 5, c = i & 31;
        *(uint4*)&smw[W_W1H + r * 36 + c] = *(const uint4*)&g_w1h[lofs + i];
        *(uint4*)&smw[W_W1L + r * 36 + c] = *(const uint4*)&g_w1l[lofs + i];
    }
    // W2 [64][68]
    for (int i = tid * 4; i < 4096; i += 1024) {
        int r = i >> 6, c = i & 63;
        *(uint4*)&smw[W_W2H + r * 68 + c] = *(const uint4*)&g_w2h[lofs + i];
        *(uint4*)&smw[W_W2L + r * 68 + c] = *(const uint4*)&g_w2l[lofs + i];
    }
    __syncthreads();

    uint32_t sb = smem_u32(smw);
    int lr = (lane & 7) + ((lane >> 3) & 1) * 8;   // A-tile row
    int lhalf = lane >> 4;                          // A k-half (16B)
    int l8 = lane & 7, lg = lane >> 3;              // B row / group

    // ---- GEMM1: C1[64x128] = U[64x64] @ W1^T ----
    uint32_t a1H = sb + W_UH * 4 + (16 * wm + lr) * 144 + lhalf * 16;
    uint32_t a1L = a1H + (W_UL - W_UH) * 4;
    uint32_t b1H = sb + W_W1H * 4 + (64 * wn + l8) * 144 + lg * 16;
    uint32_t b1L = b1H + (W_W1L - W_W1H) * 4;

    unsigned aH[4][4], aL[4][4];
#pragma unroll
    for (int ks = 0; ks < 4; ks++) {
        ldsm4(aH[ks][0], aH[ks][1], aH[ks][2], aH[ks][3], a1H + ks * 32);
        ldsm4(aL[ks][0], aL[ks][1], aL[ks][2], aL[ks][3], a1L + ks * 32);
    }
    float c1[8][4];
#pragma unroll
    for (int j = 0; j < 8; j++)
#pragma unroll
        for (int q = 0; q < 4; q++) c1[j][q] = 0.f;

#pragma unroll
    for (int j = 0; j < 8; j++) {
        uint32_t bj = b1H + j * 1152, bjL = b1L + j * 1152;   // 8 rows * 144B
#pragma unroll
        for (int p = 0; p < 2; p++) {
            unsigned h0, h1, h2, h3, l0, l1, l2, l3;
            ldsm4(h0, h1, h2, h3, bj + p * 64);
            ldsm4(l0, l1, l2, l3, bjL + p * 64);
            int ka = 2 * p, kb = 2 * p + 1;
            mma16(c1[j], aH[ka][0], aH[ka][1], aH[ka][2], aH[ka][3], h0, h1);
            mma16(c1[j], aH[ka][0], aH[ka][1], aH[ka][2], aH[ka][3], l0, l1);
            mma16(c1[j], aL[ka][0], aL[ka][1], aL[ka][2], aL[ka][3], h0, h1);
            mma16(c1[j], aH[kb][0], aH[kb][1], aH[kb][2], aH[kb][3], h2, h3);
            mma16(c1[j], aH[kb][0], aH[kb][1], aH[kb][2], aH[kb][3], l2, l3);
            mma16(c1[j], aL[kb][0], aL[kb][1], aL[kb][2], aL[kb][3], h2, h3);
        }
    }

    // ---- epilogue 1: bias + LN partial sums (regs only) ----
    int r0 = 16 * wm + g, r1 = r0 + 8;
    float sA = 0.f, sqA = 0.f, sB = 0.f, sqB = 0.f;
#pragma unroll
    for (int j = 0; j < 8; j++) {
        int cb = 64 * wn + 8 * j + 2 * t4;
        float bx = smf[W_B1 + cb], by = smf[W_B1 + cb + 1];
        c1[j][0] += bx; c1[j][1] += by; c1[j][2] += bx; c1[j][3] += by;
        sA += c1[j][0] + c1[j][1];
        sqA = fmaf(c1[j][0], c1[j][0], fmaf(c1[j][1], c1[j][1], sqA));
        sB += c1[j][2] + c1[j][3];
        sqB = fmaf(c1[j][2], c1[j][2], fmaf(c1[j][3], c1[j][3], sqB));
    }
    sA += __shfl_xor_sync(0xffffffffu, sA, 1);  sA += __shfl_xor_sync(0xffffffffu, sA, 2);
    sqA += __shfl_xor_sync(0xffffffffu, sqA, 1); sqA += __shfl_xor_sync(0xffffffffu, sqA, 2);
    sB += __shfl_xor_sync(0xffffffffu, sB, 1);  sB += __shfl_xor_sync(0xffffffffu, sB, 2);
    sqB += __shfl_xor_sync(0xffffffffu, sqB, 1); sqB += __shfl_xor_sync(0xffffffffu, sqB, 2);
    if (t4 == 0) {
        smf[W_PSUM + wn * 64 + r0] = sA;  smf[W_PSQ + wn * 64 + r0] = sqA;
        smf[W_PSUM + wn * 64 + r1] = sB;  smf[W_PSQ + wn * 64 + r1] = sqB;
    }
    __syncthreads();   // also orders U-reads before ACT overwrite

    float s0 = smf[W_PSUM + r0] + smf[W_PSUM + 64 + r0];
    float q0 = smf[W_PSQ + r0]  + smf[W_PSQ + 64 + r0];
    float s1 = smf[W_PSUM + r1] + smf[W_PSUM + 64 + r1];
    float q1 = smf[W_PSQ + r1]  + smf[W_PSQ + 64 + r1];
    float mu0 = s0 * (1.f / 128.f), mu1 = s1 * (1.f / 128.f);
    float rs0 = rsqrtf(q0 * (1.f / 128.f) - mu0 * mu0 + 1e-5f);
    float rs1 = rsqrtf(q1 * (1.f / 128.f) - mu1 * mu1 + 1e-5f);

    // ---- LN + relu + split -> ACT tiles [64][68] ----
#pragma unroll
    for (int j = 0; j < 8; j++) {
        int cb = 64 * wn + 8 * j + 2 * t4;
        float gx = smf[W_GAM + cb], gy = smf[W_GAM + cb + 1];
        float ex = smf[W_BET + cb], ey = smf[W_BET + cb + 1];
        float h0 = fmaxf((c1[j][0] - mu0) * rs0 * gx + ex, 0.f);
        float h1 = fmaxf((c1[j][1] - mu0) * rs0 * gy + ey, 0.f);
        float h2 = fmaxf((c1[j][2] - mu1) * rs1 * gx + ex, 0.f);
        float h3 = fmaxf((c1[j][3] - mu1) * rs1 * gy + ey, 0.f);
        int kp = cb >> 1;
        unsigned hw, lw;
        split_pair(h0, h1, hw, lw);
        smw[W_HH + r0 * 68 + kp] = hw; smw[W_HL + r0 * 68 + kp] = lw;
        split_pair(h2, h3, hw, lw);
        smw[W_HH + r1 * 68 + kp] = hw; smw[W_HL + r1 * 68 + kp] = lw;
    }
    __syncthreads();

    // ---- GEMM2: C2[64x64] = ACT[64x128] @ W2^T ----
    uint32_t a2H = sb + W_HH * 4 + (16 * wm + lr) * 272 + lhalf * 16;
    uint32_t a2L = a2H + (W_HL - W_HH) * 4;
    uint32_t b2H = sb + W_W2H * 4 + (32 * wn + l8) * 272 + lg * 16;
    uint32_t b2L = b2H + (W_W2L - W_W2H) * 4;

    float c2[4][4];
#pragma unroll
    for (int j = 0; j < 4; j++)
#pragma unroll
        for (int q = 0; q < 4; q++) c2[j][q] = 0.f;

#pragma unroll
    for (int p = 0; p < 4; p++) {
        unsigned xh[8], xl[8];
        ldsm4(xh[0], xh[1], xh[2], xh[3], a2H + p * 64);
        ldsm4(xh[4], xh[5], xh[6], xh[7], a2H + p * 64 + 32);
        ldsm4(xl[0], xl[1], xl[2], xl[3], a2L + p * 64);
        ldsm4(xl[4], xl[5], xl[6], xl[7], a2L + p * 64 + 32);
#pragma unroll
        for (int j = 0; j < 4; j++) {
            unsigned h0, h1, h2, h3, l0, l1, l2, l3;
            ldsm4(h0, h1, h2, h3, b2H + j * 2176 + p * 64);
            ldsm4(l0, l1, l2, l3, b2L + j * 2176 + p * 64);
            mma16(c2[j], xh[0], xh[1], xh[2], xh[3], h0, h1);
            mma16(c2[j], xh[0], xh[1], xh[2], xh[3], l0, l1);
            mma16(c2[j], xl[0], xl[1], xl[2], xl[3], h0, h1);
            mma16(c2[j], xh[4], xh[5], xh[6], xh[7], h2, h3);
            mma16(c2[j], xh[4], xh[5], xh[6], xh[7], l2, l3);
            mma16(c2[j], xl[4], xl[5], xl[6], xl[7], h2, h3);
        }
    }

    // ---- epilogue 2: bias (+residual) -> g_h ----
    int node0 = n0 + r0, node1 = n0 + r1;
#pragma unroll
    for (int j = 0; j < 4; j++) {
        int cb = 32 * wn + 8 * j + 2 * t4;
        float bx = smf[W_B2 + cb], by = smf[W_B2 + cb + 1];
        if (node0 < NN) {
            float2 o = make_float2(c2[j][0] + bx, c2[j][1] + by);
            float* dst = g_h + node0 * HH + cb;
            if (addm) { float2 pv = *(const float2*)dst; o.x += pv.x; o.y += pv.y; }
            *(float2*)dst = o;
        }
        if (node1 < NN) {
            float2 o = make_float2(c2[j][2] + bx, c2[j][3] + by);
            float* dst = g_h + node1 * HH + cb;
            if (addm) { float2 pv = *(const float2*)dst; o.x += pv.x; o.y += pv.y; }
            *(float2*)dst = o;
        }
    }
}

// -------- final: relu(LN(h)) @ lin_W + lin_b ; also re-zero scratch --------
__global__ void k_final(const float* __restrict__ g, const float* __restrict__ b,
                        const float* __restrict__ lw, const float* __restrict__ lb,
                        float* __restrict__ out) {
    int gw = (blockIdx.x * blockDim.x + threadIdx.x) >> 5;
    if (gw >= NN) return;
    int lane = threadIdx.x & 31;
    if (lane == 1) g_wp[gw] = 0;
    if (gw < 128 && lane == 2) g_sflag[gw] = 0;

    float2 v = *(const float2*)(g_h + gw * HH + 2 * lane);
    float s = v.x + v.y, sq = v.x * v.x + v.y * v.y;
    for (int o = 16; o; o >>= 1) {
        s  += __shfl_xor_sync(0xffffffffu, s, o);
        sq += __shfl_xor_sync(0xffffffffu, sq, o);
    }
    float mu = s * 0.015625f;
    float var = sq * 0.015625f - mu * mu;
    float rs = rsqrtf(var + 1e-5f);
    float a0 = fmaxf((v.x - mu) * rs * g[2 * lane]     + b[2 * lane],     0.f);
    float a1 = fmaxf((v.y - mu) * rs * g[2 * lane + 1] + b[2 * lane + 1], 0.f);
    float o0 = a0 * lw[(2 * lane) * 3 + 0] + a1 * lw[(2 * lane + 1) * 3 + 0];
    float o1 = a0 * lw[(2 * lane) * 3 + 1] + a1 * lw[(2 * lane + 1) * 3 + 1];
    float o2 = a0 * lw[(2 * lane) * 3 + 2] + a1 * lw[(2 * lane + 1) * 3 + 2];
    for (int ww = 16; ww; ww >>= 1) {
        o0 += __shfl_xor_sync(0xffffffffu, o0, ww);
        o1 += __shfl_xor_sync(0xffffffffu, o1, ww);
        o2 += __shfl_xor_sync(0xffffffffu, o2, ww);
    }
    if (lane == 0) {
        out[gw * 3 + 0] = o0 + lb[0];
        out[gw * 3 + 1] = o1 + lb[1];
        out[gw * 3 + 2] = o2 + lb[2];
    }
}

// ---------------- launch ----------------
extern "C" void kernel_launch(void* const* d_in, const int* in_sizes, int n_in,
                              void* d_out, int out_size) {
    const float* x    = (const float*)d_in[0];
    const int*   ei   = (const int*)  d_in[1];
    const float* encW = (const float*)d_in[2];
    const float* encb = (const float*)d_in[3];
    const float* t    = (const float*)d_in[4];
    const float* W1   = (const float*)d_in[5];
    const float* b1   = (const float*)d_in[6];
    const float* mg   = (const float*)d_in[7];
    const float* mb   = (const float*)d_in[8];
    const float* W2   = (const float*)d_in[9];
    const float* b2   = (const float*)d_in[10];
    const float* lng  = (const float*)d_in[11];
    const float* lnb  = (const float*)d_in[12];
    const float* lw   = (const float*)d_in[13];
    const float* lb   = (const float*)d_in[14];
    float* out = (float*)d_out;

    cudaFuncSetAttribute(k_mlp, cudaFuncAttributeMaxDynamicSharedMemorySize, SMEM_MLP_BYTES);

    const int WARP_BLOCKS = (NN * 32 + 255) / 256;
    const int MLP_BLOCKS  = (NN + 63) / 64;

    // CSR build + encoder + weight pre-split (launches 0..2)
    k_enc_hist<<<(NN * HH + 255) / 256, 256>>>(x, encW, encb, ei, W1, W2);
    k_scan<<<NB_SCAN, 1024>>>();
    k_scatter<<<(NE + 255) / 256, 256>>>(ei);

    // layer 0 (launch index 3 = k_agg -> profiled slot)
    k_agg<<<WARP_BLOCKS, 256>>>(t + 0);
    k_mlp<<<MLP_BLOCKS, 256, SMEM_MLP_BYTES>>>(b1, mg, mb, b2, 0, 0);

    // layers 1, 2
    for (int i = 1; i < 3; i++) {
        k_lnrelu<<<WARP_BLOCKS, 256>>>(lng + i * HH, lnb + i * HH);
        k_agg<<<WARP_BLOCKS, 256>>>(t + i);
        k_mlp<<<MLP_BLOCKS, 256, SMEM_MLP_BYTES>>>(b1 + i * H2, mg + i * H2, mb + i * H2,
                                                   b2 + i * HH, i, 1);
    }

    // final projection (+ scratch re-zero for next replay)
    k_final<<<WARP_BLOCKS, 256>>>(lng, lnb, lw, lb, out);
}